// round 1
// baseline (speedup 1.0000x reference)
#include <cuda_runtime.h>
#include <math.h>

// Problem constants
constexpr int Bn  = 4;
constexpr int Sn  = 2048;
constexpr int Dn  = 1024;
constexpr int Hn  = 16;
constexpr int HDn = 64;
constexpr int FFn = 4096;
constexpr int Mn  = Bn * Sn;        // 8192 rows
constexpr float NEG_INF = -1.0e30f;

// ---------------- scratch (static __device__, no allocations) ----------------
__device__ float g_Wqkv[Dn * 3 * Dn];   // [K=1024][N=3072] packed q|k|v
__device__ float g_Bqkv[3 * Dn];
__device__ float g_QKV [(size_t)Mn * 3 * Dn];  // [8192][3072] q|k|v per row
__device__ float g_O   [(size_t)Mn * Dn];      // attention output [B,S,D]
__device__ float g_T   [(size_t)Mn * Dn];      // residual temp
__device__ float g_Hh  [(size_t)Mn * Dn];      // post-LN1 hidden
__device__ float g_FF  [(size_t)Mn * FFn];     // FFN intermediate

// ---------------- weight repack: wq/wk/wv [H,D,HD] -> [D, 3*1024] ------------
__global__ void repack_qkv(const float* __restrict__ wq, const float* __restrict__ wk,
                           const float* __restrict__ wv, const float* __restrict__ bq,
                           const float* __restrict__ bk, const float* __restrict__ bv) {
    int gid = blockIdx.x * blockDim.x + threadIdx.x;
    const int total = Dn * 3 * Dn;
    if (gid < total) {
        int d     = gid / (3 * Dn);
        int col   = gid - d * (3 * Dn);
        int which = col >> 10;          // 0=q, 1=k, 2=v
        int c     = col & 1023;         // h*64 + f
        int h     = c >> 6, f = c & 63;
        const float* w = (which == 0) ? wq : (which == 1) ? wk : wv;
        g_Wqkv[gid] = w[((size_t)h * Dn + d) * HDn + f];
    }
    if (gid < 3 * Dn) {
        int which = gid >> 10; int c = gid & 1023;
        const float* b = (which == 0) ? bq : (which == 1) ? bk : bv;
        g_Bqkv[gid] = b[c];
    }
}

// ---------------- SGEMM 128x128x16, 256 threads, 8x8 microtile ---------------
enum { EPI_BIAS = 0, EPI_GELU = 1, EPI_RES = 2 };

__device__ __forceinline__ float gelu_f(float x) {
    return 0.5f * x * (1.0f + erff(x * 0.70710678118654752440f));
}

template <int EPI>
__global__ void __launch_bounds__(256, 2)
sgemm(const float* __restrict__ A, const float* __restrict__ Bm,
      const float* __restrict__ bias, const float* __restrict__ Res,
      float* __restrict__ C, int M, int N, int K) {
    __shared__ float As[16][132];   // transposed A tile (padded)
    __shared__ float Bs[16][128];

    const int tid = threadIdx.x;
    const int tm = tid >> 4, tn = tid & 15;
    const int m0 = blockIdx.y * 128, n0 = blockIdx.x * 128;

    float acc[8][8] = {};

    for (int k0 = 0; k0 < K; k0 += 16) {
        // load A tile (transpose into As[k][m])
        #pragma unroll
        for (int ld = 0; ld < 2; ld++) {
            int id  = tid + ld * 256;          // 0..511 float4 slots
            int row = id >> 2;
            int kq  = (id & 3) * 4;
            float4 v = *(const float4*)&A[(size_t)(m0 + row) * K + k0 + kq];
            As[kq + 0][row] = v.x; As[kq + 1][row] = v.y;
            As[kq + 2][row] = v.z; As[kq + 3][row] = v.w;
        }
        // load B tile
        #pragma unroll
        for (int ld = 0; ld < 2; ld++) {
            int id = tid + ld * 256;
            int kk = id >> 5;
            int n4 = (id & 31) * 4;
            *(float4*)&Bs[kk][n4] = *(const float4*)&Bm[(size_t)(k0 + kk) * N + n0 + n4];
        }
        __syncthreads();

        #pragma unroll
        for (int kk = 0; kk < 16; kk++) {
            float4 a0 = *(float4*)&As[kk][tm * 8];
            float4 a1 = *(float4*)&As[kk][tm * 8 + 4];
            float4 b0 = *(float4*)&Bs[kk][tn * 8];
            float4 b1 = *(float4*)&Bs[kk][tn * 8 + 4];
            float av[8] = {a0.x, a0.y, a0.z, a0.w, a1.x, a1.y, a1.z, a1.w};
            float bw[8] = {b0.x, b0.y, b0.z, b0.w, b1.x, b1.y, b1.z, b1.w};
            #pragma unroll
            for (int i = 0; i < 8; i++)
                #pragma unroll
                for (int j = 0; j < 8; j++)
                    acc[i][j] += av[i] * bw[j];
        }
        __syncthreads();
    }

    // epilogue
    #pragma unroll
    for (int i = 0; i < 8; i++) {
        int m = m0 + tm * 8 + i;
        size_t base = (size_t)m * N + n0 + tn * 8;
        #pragma unroll
        for (int j = 0; j < 8; j += 4) {
            int n = n0 + tn * 8 + j;
            float4 r;
            r.x = acc[i][j + 0] + bias[n + 0];
            r.y = acc[i][j + 1] + bias[n + 1];
            r.z = acc[i][j + 2] + bias[n + 2];
            r.w = acc[i][j + 3] + bias[n + 3];
            if (EPI == EPI_GELU) {
                r.x = gelu_f(r.x); r.y = gelu_f(r.y);
                r.z = gelu_f(r.z); r.w = gelu_f(r.w);
            } else if (EPI == EPI_RES) {
                float4 rr = *(const float4*)&Res[base + j];
                r.x += rr.x; r.y += rr.y; r.z += rr.z; r.w += rr.w;
            }
            *(float4*)&C[base + j] = r;
        }
    }
}

// ---------------- causal flash attention, 1 query row per thread -------------
// Q,K,V live in g_QKV rows of 3072 floats (q|k|v), head h at offset h*64.
__global__ void __launch_bounds__(128, 2)
attn_kernel(const float* __restrict__ QKV, float* __restrict__ O) {
    __shared__ float Ks[64][64];
    __shared__ float Vs[64][64];

    const int t  = threadIdx.x;
    const int r0 = blockIdx.x * 128;
    const int bh = blockIdx.y;
    const int b  = bh >> 4, h = bh & 15;
    const int r  = r0 + t;                       // this thread's query row

    const float* qptr = QKV + ((size_t)(b * Sn + r)) * 3072 + h * 64;
    float q[64], o[64];
    #pragma unroll
    for (int d4 = 0; d4 < 16; d4++) {
        float4 v = *(const float4*)(qptr + d4 * 4);
        q[d4 * 4 + 0] = v.x * 0.125f;   // fold 1/sqrt(64)
        q[d4 * 4 + 1] = v.y * 0.125f;
        q[d4 * 4 + 2] = v.z * 0.125f;
        q[d4 * 4 + 3] = v.w * 0.125f;
    }
    #pragma unroll
    for (int d = 0; d < 64; d++) o[d] = 0.0f;
    float mrun = NEG_INF, lrun = 0.0f;

    const int ntiles = (r0 >> 6) + 2;            // keys up to r0+127
    for (int kt = 0; kt < ntiles; kt++) {
        const int base = kt * 64;
        const float* kg = QKV + ((size_t)(b * Sn + base)) * 3072 + 1024 + h * 64;
        const float* vg = kg + 1024;
        #pragma unroll
        for (int w = 0; w < 8; w++) {
            int idx = t + w * 128;               // 0..1023 float4 slots
            int j = idx >> 4, d4 = idx & 15;
            *(float4*)&Ks[j][d4 * 4] = *(const float4*)(kg + (size_t)j * 3072 + d4 * 4);
            *(float4*)&Vs[j][d4 * 4] = *(const float4*)(vg + (size_t)j * 3072 + d4 * 4);
        }
        __syncthreads();

        #pragma unroll 1
        for (int c = 0; c < 4; c++) {
            const int gk0 = base + c * 16;
            if (gk0 > r) break;                  // fully masked chunk

            float sarr[16];
            #pragma unroll
            for (int jj = 0; jj < 16; jj++) {
                const float4* kp = (const float4*)&Ks[c * 16 + jj][0];
                float s0 = 0.f, s1 = 0.f, s2 = 0.f, s3 = 0.f;
                #pragma unroll
                for (int dq = 0; dq < 4; dq++) {
                    float4 k0 = kp[dq * 4 + 0];
                    float4 k1 = kp[dq * 4 + 1];
                    float4 k2 = kp[dq * 4 + 2];
                    float4 k3 = kp[dq * 4 + 3];
                    const float* qq = &q[dq * 16];
                    s0 += qq[0]  * k0.x + qq[1]  * k0.y + qq[2]  * k0.z + qq[3]  * k0.w;
                    s1 += qq[4]  * k1.x + qq[5]  * k1.y + qq[6]  * k1.z + qq[7]  * k1.w;
                    s2 += qq[8]  * k2.x + qq[9]  * k2.y + qq[10] * k2.z + qq[11] * k2.w;
                    s3 += qq[12] * k3.x + qq[13] * k3.y + qq[14] * k3.z + qq[15] * k3.w;
                }
                sarr[jj] = (s0 + s1) + (s2 + s3);
            }
            #pragma unroll
            for (int jj = 0; jj < 16; jj++)
                if (gk0 + jj > r) sarr[jj] = NEG_INF;

            float cm = sarr[0];
            #pragma unroll
            for (int jj = 1; jj < 16; jj++) cm = fmaxf(cm, sarr[jj]);

            if (cm > mrun) {                     // rescale only when max moves
                float scale = __expf(mrun - cm); // mrun=-1e30 -> 0
                lrun *= scale;
                #pragma unroll
                for (int d = 0; d < 64; d++) o[d] *= scale;
                mrun = cm;
            }
            #pragma unroll
            for (int jj = 0; jj < 16; jj++) {
                float p = __expf(sarr[jj] - mrun);   // masked -> 0
                lrun += p;
                const float4* vp = (const float4*)&Vs[c * 16 + jj][0];
                #pragma unroll
                for (int d4 = 0; d4 < 16; d4++) {
                    float4 vv = vp[d4];
                    o[d4 * 4 + 0] += p * vv.x;
                    o[d4 * 4 + 1] += p * vv.y;
                    o[d4 * 4 + 2] += p * vv.z;
                    o[d4 * 4 + 3] += p * vv.w;
                }
            }
        }
        __syncthreads();
    }

    const float inv = 1.0f / lrun;
    float* optr = O + ((size_t)(b * Sn + r)) * Dn + h * 64;
    #pragma unroll
    for (int d4 = 0; d4 < 16; d4++) {
        float4 v;
        v.x = o[d4 * 4 + 0] * inv;
        v.y = o[d4 * 4 + 1] * inv;
        v.z = o[d4 * 4 + 2] * inv;
        v.w = o[d4 * 4 + 3] * inv;
        *(float4*)(optr + d4 * 4) = v;
    }
}

// ---------------- LayerNorm: one block per row of 1024 -----------------------
__global__ void __launch_bounds__(256)
ln_kernel(const float* __restrict__ X, const float* __restrict__ G,
          const float* __restrict__ Bt, float* __restrict__ Y) {
    const int row = blockIdx.x;
    const int t = threadIdx.x;
    const float* x = X + (size_t)row * Dn;

    float4 v = *(const float4*)(x + t * 4);
    float s  = v.x + v.y + v.z + v.w;
    float sq = v.x * v.x + v.y * v.y + v.z * v.z + v.w * v.w;
    #pragma unroll
    for (int off = 16; off; off >>= 1) {
        s  += __shfl_xor_sync(0xffffffffu, s,  off);
        sq += __shfl_xor_sync(0xffffffffu, sq, off);
    }
    __shared__ float rs[8], rq[8];
    int wid = t >> 5, lane = t & 31;
    if (lane == 0) { rs[wid] = s; rq[wid] = sq; }
    __syncthreads();
    if (t == 0) {
        float S = 0.f, Q = 0.f;
        #pragma unroll
        for (int i = 0; i < 8; i++) { S += rs[i]; Q += rq[i]; }
        float mean = S * (1.0f / Dn);
        float var  = Q * (1.0f / Dn) - mean * mean;
        rs[0] = mean;
        rq[0] = rsqrtf(var + 1e-5f);
    }
    __syncthreads();
    const float mean = rs[0], rstd = rq[0];

    float4 gv = *(const float4*)(G + t * 4);
    float4 bv = *(const float4*)(Bt + t * 4);
    float4 y;
    y.x = (v.x - mean) * rstd * gv.x + bv.x;
    y.y = (v.y - mean) * rstd * gv.y + bv.y;
    y.z = (v.z - mean) * rstd * gv.z + bv.z;
    y.w = (v.w - mean) * rstd * gv.w + bv.w;
    *(float4*)(Y + (size_t)row * Dn + t * 4) = y;
}

// ---------------- launch ----------------
extern "C" void kernel_launch(void* const* d_in, const int* in_sizes, int n_in,
                              void* d_out, int out_size) {
    const float* x   = (const float*)d_in[0];
    const float* wq  = (const float*)d_in[1];
    const float* bq  = (const float*)d_in[2];
    const float* wk  = (const float*)d_in[3];
    const float* bk  = (const float*)d_in[4];
    const float* wv  = (const float*)d_in[5];
    const float* bv  = (const float*)d_in[6];
    const float* wo  = (const float*)d_in[7];
    const float* bo  = (const float*)d_in[8];
    const float* w1  = (const float*)d_in[9];
    const float* b1  = (const float*)d_in[10];
    const float* w2  = (const float*)d_in[11];
    const float* b2  = (const float*)d_in[12];
    const float* g1  = (const float*)d_in[13];
    const float* be1 = (const float*)d_in[14];
    const float* g2  = (const float*)d_in[15];
    const float* be2 = (const float*)d_in[16];

    float *Wqkv, *Bqkv, *QKV, *O, *T, *Hh, *FF;
    cudaGetSymbolAddress((void**)&Wqkv, g_Wqkv);
    cudaGetSymbolAddress((void**)&Bqkv, g_Bqkv);
    cudaGetSymbolAddress((void**)&QKV,  g_QKV);
    cudaGetSymbolAddress((void**)&O,    g_O);
    cudaGetSymbolAddress((void**)&T,    g_T);
    cudaGetSymbolAddress((void**)&Hh,   g_Hh);
    cudaGetSymbolAddress((void**)&FF,   g_FF);

    // 1) fold wq/wk/wv -> one [1024,3072] weight
    repack_qkv<<<(Dn * 3 * Dn + 255) / 256, 256>>>(wq, wk, wv, bq, bk, bv);
    // 2) QKV projection: [8192,3072]
    sgemm<EPI_BIAS><<<dim3(3 * Dn / 128, Mn / 128), 256>>>(x, Wqkv, Bqkv, nullptr, QKV, Mn, 3 * Dn, Dn);
    // 3) causal flash attention -> O [B,S,D]
    attn_kernel<<<dim3(Sn / 128, Bn * Hn), 128>>>(QKV, O);
    // 4) O projection + residual x
    sgemm<EPI_RES><<<dim3(Dn / 128, Mn / 128), 256>>>(O, wo, bo, x, T, Mn, Dn, Dn);
    // 5) LayerNorm 1
    ln_kernel<<<Mn, 256>>>(T, g1, be1, Hh);
    // 6) FFN up + exact GELU
    sgemm<EPI_GELU><<<dim3(FFn / 128, Mn / 128), 256>>>(Hh, w1, b1, nullptr, FF, Mn, FFn, Dn);
    // 7) FFN down + residual h
    sgemm<EPI_RES><<<dim3(Dn / 128, Mn / 128), 256>>>(FF, w2, b2, Hh, T, Mn, Dn, FFn);
    // 8) LayerNorm 2 -> output
    ln_kernel<<<Mn, 256>>>(T, g2, be2, (float*)d_out);
}

// round 2
// speedup vs baseline: 3.1038x; 3.1038x over previous
#include <cuda_runtime.h>
#include <math.h>

// Problem constants
constexpr int Bn  = 4;
constexpr int Sn  = 2048;
constexpr int Dn  = 1024;
constexpr int Hn  = 16;
constexpr int HDn = 64;
constexpr int FFn = 4096;
constexpr int Mn  = Bn * Sn;        // 8192 rows
constexpr float NEG_INF = -1.0e30f;

// ---------------- scratch (static __device__, no allocations) ----------------
__device__ float g_Wqkv[Dn * 3 * Dn];   // [K=1024][N=3072] packed q|k|v
__device__ float g_Bqkv[3 * Dn];
__device__ float g_QKV [(size_t)Mn * 3 * Dn];  // [8192][3072] q|k|v per row
__device__ float g_O   [(size_t)Mn * Dn];      // attention output [B,S,D]
__device__ float g_T   [(size_t)Mn * Dn];      // residual temp
__device__ float g_Hh  [(size_t)Mn * Dn];      // post-LN1 hidden
__device__ float g_FF  [(size_t)Mn * FFn];     // FFN intermediate

// ---------------- weight repack: wq/wk/wv [H,D,HD] -> [D, 3*1024] ------------
__global__ void repack_qkv(const float* __restrict__ wq, const float* __restrict__ wk,
                           const float* __restrict__ wv, const float* __restrict__ bq,
                           const float* __restrict__ bk, const float* __restrict__ bv) {
    int gid = blockIdx.x * blockDim.x + threadIdx.x;
    const int total = Dn * 3 * Dn;
    if (gid < total) {
        int d     = gid / (3 * Dn);
        int col   = gid - d * (3 * Dn);
        int which = col >> 10;          // 0=q, 1=k, 2=v
        int c     = col & 1023;         // h*64 + f
        int h     = c >> 6, f = c & 63;
        const float* w = (which == 0) ? wq : (which == 1) ? wk : wv;
        g_Wqkv[gid] = w[((size_t)h * Dn + d) * HDn + f];
    }
    if (gid < 3 * Dn) {
        int which = gid >> 10; int c = gid & 1023;
        const float* b = (which == 0) ? bq : (which == 1) ? bk : bv;
        g_Bqkv[gid] = b[c];
    }
}

// ---------------- tf32 tensor-core GEMM 128x128x16 ---------------------------
// 256 threads = 8 warps in 2(m) x 4(n); warp tile 64x32 = 4x4 m16n8k8 tiles.
// A smem: m-major [128][20]  (stride 20 -> conflict-free A-fragment LDS)
// B smem: k-major [16][136]  (stride 136 -> conflict-free B-fragment LDS)
enum { EPI_BIAS = 0, EPI_GELU = 1, EPI_RES = 2 };

__device__ __forceinline__ float gelu_f(float x) {
    return 0.5f * x * (1.0f + erff(x * 0.70710678118654752440f));
}

__device__ __forceinline__ float4 cvt_tf32_4(float4 v) {
    asm("cvt.rna.tf32.f32 %0, %0;" : "+f"(v.x));
    asm("cvt.rna.tf32.f32 %0, %0;" : "+f"(v.y));
    asm("cvt.rna.tf32.f32 %0, %0;" : "+f"(v.z));
    asm("cvt.rna.tf32.f32 %0, %0;" : "+f"(v.w));
    return v;
}

__device__ __forceinline__ void mma_tf32(float* c, const float* a, const float* b) {
    asm volatile(
        "mma.sync.aligned.m16n8k8.row.col.f32.tf32.tf32.f32 "
        "{%0,%1,%2,%3}, {%4,%5,%6,%7}, {%8,%9}, {%0,%1,%2,%3};"
        : "+f"(c[0]), "+f"(c[1]), "+f"(c[2]), "+f"(c[3])
        : "r"(__float_as_uint(a[0])), "r"(__float_as_uint(a[1])),
          "r"(__float_as_uint(a[2])), "r"(__float_as_uint(a[3])),
          "r"(__float_as_uint(b[0])), "r"(__float_as_uint(b[1])));
}

constexpr int ASTR = 20;    // A smem row stride (floats)
constexpr int BSTR = 136;   // B smem row stride (floats)

template <int EPI>
__global__ void __launch_bounds__(256, 2)
tgemm(const float* __restrict__ A, const float* __restrict__ Bm,
      const float* __restrict__ bias, const float* __restrict__ Res,
      float* __restrict__ C, int M, int N, int K) {
    __shared__ float As[2][128 * ASTR];
    __shared__ float Bs[2][16 * BSTR];

    const int tid  = threadIdx.x;
    const int lane = tid & 31, wid = tid >> 5;
    const int quad = lane >> 2, qt = lane & 3;
    const int wm = wid & 1, wn = wid >> 1;
    const int m0 = blockIdx.y * 128, n0 = blockIdx.x * 128;

    // global load assignments
    const float* Ag = A  + (size_t)(m0 + (tid >> 2)) * K + (tid & 3) * 4;
    const float* Bg = Bm + (size_t)(tid >> 5) * N + n0 + (tid & 31) * 4;

    float acc[4][4][4] = {};

    float4 a0v, a1v, b0v, b1v;
    // prologue: LDG tile 0
    a0v = *(const float4*)(Ag);
    a1v = *(const float4*)(Ag + (size_t)64 * K);
    b0v = *(const float4*)(Bg);
    b1v = *(const float4*)(Bg + (size_t)8 * N);

    // STS helper offsets
    float* apS = nullptr; float* bpS = nullptr;
    const int aOff = (tid >> 2) * ASTR + (tid & 3) * 4;
    const int bOff = (tid >> 5) * BSTR + (tid & 31) * 4;

    // store tile 0 into buffer 0 (with tf32 rounding)
    apS = &As[0][aOff]; bpS = &Bs[0][bOff];
    *(float4*)apS                 = cvt_tf32_4(a0v);
    *(float4*)(apS + 64 * ASTR)   = cvt_tf32_4(a1v);
    *(float4*)bpS                 = cvt_tf32_4(b0v);
    *(float4*)(bpS + 8 * BSTR)    = cvt_tf32_4(b1v);
    __syncthreads();

    const int niter = K >> 4;
    int buf = 0;

    for (int it = 0; it < niter; it++) {
        // prefetch next tile into registers (overlaps with compute below)
        if (it + 1 < niter) {
            const float* An = Ag + (it + 1) * 16;
            const float* Bnp = Bg + (size_t)(it + 1) * 16 * N;
            a0v = *(const float4*)(An);
            a1v = *(const float4*)(An + (size_t)64 * K);
            b0v = *(const float4*)(Bnp);
            b1v = *(const float4*)(Bnp + (size_t)8 * N);
        }

        // compute on current buffer
        const float* Ab = As[buf];
        const float* Bb = Bs[buf];
        #pragma unroll
        for (int ks = 0; ks < 2; ks++) {
            const int kb = ks * 8;
            float af[4][4];
            float bf[4][2];
            #pragma unroll
            for (int mt = 0; mt < 4; mt++) {
                const float* p = Ab + (wm * 64 + mt * 16 + quad) * ASTR + kb + qt;
                af[mt][0] = p[0];
                af[mt][1] = p[8 * ASTR];
                af[mt][2] = p[4];
                af[mt][3] = p[8 * ASTR + 4];
            }
            #pragma unroll
            for (int nt = 0; nt < 4; nt++) {
                const float* p = Bb + (kb + qt) * BSTR + wn * 32 + nt * 8 + quad;
                bf[nt][0] = p[0];
                bf[nt][1] = p[4 * BSTR];
            }
            #pragma unroll
            for (int mt = 0; mt < 4; mt++)
                #pragma unroll
                for (int nt = 0; nt < 4; nt++)
                    mma_tf32(acc[mt][nt], af[mt], bf[nt]);
        }

        if (it + 1 < niter) {
            // write next tile into the other buffer; safe: all warps finished
            // reading it (barrier at end of previous iteration)
            apS = &As[buf ^ 1][aOff]; bpS = &Bs[buf ^ 1][bOff];
            *(float4*)apS               = cvt_tf32_4(a0v);
            *(float4*)(apS + 64 * ASTR) = cvt_tf32_4(a1v);
            *(float4*)bpS               = cvt_tf32_4(b0v);
            *(float4*)(bpS + 8 * BSTR)  = cvt_tf32_4(b1v);
            __syncthreads();
            buf ^= 1;
        }
    }

    // epilogue: each thread owns pairs (quad, qt*2..+1) in each 16x8 tile
    #pragma unroll
    for (int mt = 0; mt < 4; mt++) {
        const int r0 = m0 + wm * 64 + mt * 16 + quad;
        #pragma unroll
        for (int nt = 0; nt < 4; nt++) {
            const int col = n0 + wn * 32 + nt * 8 + qt * 2;
            const float2 bv = *(const float2*)&bias[col];
            #pragma unroll
            for (int half = 0; half < 2; half++) {
                const int r = r0 + half * 8;
                float2 y;
                y.x = acc[mt][nt][half * 2 + 0] + bv.x;
                y.y = acc[mt][nt][half * 2 + 1] + bv.y;
                size_t base = (size_t)r * N + col;
                if (EPI == EPI_GELU) {
                    y.x = gelu_f(y.x); y.y = gelu_f(y.y);
                } else if (EPI == EPI_RES) {
                    float2 rr = *(const float2*)&Res[base];
                    y.x += rr.x; y.y += rr.y;
                }
                *(float2*)&C[base] = y;
            }
        }
    }
}

// ---------------- causal flash attention, 1 query row per thread -------------
__global__ void __launch_bounds__(128, 2)
attn_kernel(const float* __restrict__ QKV, float* __restrict__ O) {
    __shared__ float Ks[64][64];
    __shared__ float Vs[64][64];

    const int t  = threadIdx.x;
    const int r0 = blockIdx.x * 128;
    const int bh = blockIdx.y;
    const int b  = bh >> 4, h = bh & 15;
    const int r  = r0 + t;                       // this thread's query row

    const float* qptr = QKV + ((size_t)(b * Sn + r)) * 3072 + h * 64;
    float q[64], o[64];
    #pragma unroll
    for (int d4 = 0; d4 < 16; d4++) {
        float4 v = *(const float4*)(qptr + d4 * 4);
        q[d4 * 4 + 0] = v.x * 0.125f;   // fold 1/sqrt(64)
        q[d4 * 4 + 1] = v.y * 0.125f;
        q[d4 * 4 + 2] = v.z * 0.125f;
        q[d4 * 4 + 3] = v.w * 0.125f;
    }
    #pragma unroll
    for (int d = 0; d < 64; d++) o[d] = 0.0f;
    float mrun = NEG_INF, lrun = 0.0f;

    const int ntiles = (r0 >> 6) + 2;            // keys up to r0+127
    for (int kt = 0; kt < ntiles; kt++) {
        const int base = kt * 64;
        const float* kg = QKV + ((size_t)(b * Sn + base)) * 3072 + 1024 + h * 64;
        const float* vg = kg + 1024;
        #pragma unroll
        for (int w = 0; w < 8; w++) {
            int idx = t + w * 128;               // 0..1023 float4 slots
            int j = idx >> 4, d4 = idx & 15;
            *(float4*)&Ks[j][d4 * 4] = *(const float4*)(kg + (size_t)j * 3072 + d4 * 4);
            *(float4*)&Vs[j][d4 * 4] = *(const float4*)(vg + (size_t)j * 3072 + d4 * 4);
        }
        __syncthreads();

        #pragma unroll 1
        for (int c = 0; c < 4; c++) {
            const int gk0 = base + c * 16;
            if (gk0 > r) break;                  // fully masked chunk

            float sarr[16];
            #pragma unroll
            for (int jj = 0; jj < 16; jj++) {
                const float4* kp = (const float4*)&Ks[c * 16 + jj][0];
                float s0 = 0.f, s1 = 0.f, s2 = 0.f, s3 = 0.f;
                #pragma unroll
                for (int dq = 0; dq < 4; dq++) {
                    float4 k0 = kp[dq * 4 + 0];
                    float4 k1 = kp[dq * 4 + 1];
                    float4 k2 = kp[dq * 4 + 2];
                    float4 k3 = kp[dq * 4 + 3];
                    const float* qq = &q[dq * 16];
                    s0 += qq[0]  * k0.x + qq[1]  * k0.y + qq[2]  * k0.z + qq[3]  * k0.w;
                    s1 += qq[4]  * k1.x + qq[5]  * k1.y + qq[6]  * k1.z + qq[7]  * k1.w;
                    s2 += qq[8]  * k2.x + qq[9]  * k2.y + qq[10] * k2.z + qq[11] * k2.w;
                    s3 += qq[12] * k3.x + qq[13] * k3.y + qq[14] * k3.z + qq[15] * k3.w;
                }
                sarr[jj] = (s0 + s1) + (s2 + s3);
            }
            #pragma unroll
            for (int jj = 0; jj < 16; jj++)
                if (gk0 + jj > r) sarr[jj] = NEG_INF;

            float cm = sarr[0];
            #pragma unroll
            for (int jj = 1; jj < 16; jj++) cm = fmaxf(cm, sarr[jj]);

            if (cm > mrun) {                     // rescale only when max moves
                float scale = __expf(mrun - cm); // mrun=-1e30 -> 0
                lrun *= scale;
                #pragma unroll
                for (int d = 0; d < 64; d++) o[d] *= scale;
                mrun = cm;
            }
            #pragma unroll
            for (int jj = 0; jj < 16; jj++) {
                float p = __expf(sarr[jj] - mrun);   // masked -> 0
                lrun += p;
                const float4* vp = (const float4*)&Vs[c * 16 + jj][0];
                #pragma unroll
                for (int d4 = 0; d4 < 16; d4++) {
                    float4 vv = vp[d4];
                    o[d4 * 4 + 0] += p * vv.x;
                    o[d4 * 4 + 1] += p * vv.y;
                    o[d4 * 4 + 2] += p * vv.z;
                    o[d4 * 4 + 3] += p * vv.w;
                }
            }
        }
        __syncthreads();
    }

    const float inv = 1.0f / lrun;
    float* optr = O + ((size_t)(b * Sn + r)) * Dn + h * 64;
    #pragma unroll
    for (int d4 = 0; d4 < 16; d4++) {
        float4 v;
        v.x = o[d4 * 4 + 0] * inv;
        v.y = o[d4 * 4 + 1] * inv;
        v.z = o[d4 * 4 + 2] * inv;
        v.w = o[d4 * 4 + 3] * inv;
        *(float4*)(optr + d4 * 4) = v;
    }
}

// ---------------- LayerNorm: one block per row of 1024 -----------------------
__global__ void __launch_bounds__(256)
ln_kernel(const float* __restrict__ X, const float* __restrict__ G,
          const float* __restrict__ Bt, float* __restrict__ Y) {
    const int row = blockIdx.x;
    const int t = threadIdx.x;
    const float* x = X + (size_t)row * Dn;

    float4 v = *(const float4*)(x + t * 4);
    float s  = v.x + v.y + v.z + v.w;
    float sq = v.x * v.x + v.y * v.y + v.z * v.z + v.w * v.w;
    #pragma unroll
    for (int off = 16; off; off >>= 1) {
        s  += __shfl_xor_sync(0xffffffffu, s,  off);
        sq += __shfl_xor_sync(0xffffffffu, sq, off);
    }
    __shared__ float rs[8], rq[8];
    int wid = t >> 5, lane = t & 31;
    if (lane == 0) { rs[wid] = s; rq[wid] = sq; }
    __syncthreads();
    if (t == 0) {
        float S = 0.f, Q = 0.f;
        #pragma unroll
        for (int i = 0; i < 8; i++) { S += rs[i]; Q += rq[i]; }
        float mean = S * (1.0f / Dn);
        float var  = Q * (1.0f / Dn) - mean * mean;
        rs[0] = mean;
        rq[0] = rsqrtf(var + 1e-5f);
    }
    __syncthreads();
    const float mean = rs[0], rstd = rq[0];

    float4 gv = *(const float4*)(G + t * 4);
    float4 bv = *(const float4*)(Bt + t * 4);
    float4 y;
    y.x = (v.x - mean) * rstd * gv.x + bv.x;
    y.y = (v.y - mean) * rstd * gv.y + bv.y;
    y.z = (v.z - mean) * rstd * gv.z + bv.z;
    y.w = (v.w - mean) * rstd * gv.w + bv.w;
    *(float4*)(Y + (size_t)row * Dn + t * 4) = y;
}

// ---------------- launch ----------------
extern "C" void kernel_launch(void* const* d_in, const int* in_sizes, int n_in,
                              void* d_out, int out_size) {
    const float* x   = (const float*)d_in[0];
    const float* wq  = (const float*)d_in[1];
    const float* bq  = (const float*)d_in[2];
    const float* wk  = (const float*)d_in[3];
    const float* bk  = (const float*)d_in[4];
    const float* wv  = (const float*)d_in[5];
    const float* bv  = (const float*)d_in[6];
    const float* wo  = (const float*)d_in[7];
    const float* bo  = (const float*)d_in[8];
    const float* w1  = (const float*)d_in[9];
    const float* b1  = (const float*)d_in[10];
    const float* w2  = (const float*)d_in[11];
    const float* b2  = (const float*)d_in[12];
    const float* g1  = (const float*)d_in[13];
    const float* be1 = (const float*)d_in[14];
    const float* g2  = (const float*)d_in[15];
    const float* be2 = (const float*)d_in[16];

    float *Wqkv, *Bqkv, *QKV, *O, *T, *Hh, *FF;
    cudaGetSymbolAddress((void**)&Wqkv, g_Wqkv);
    cudaGetSymbolAddress((void**)&Bqkv, g_Bqkv);
    cudaGetSymbolAddress((void**)&QKV,  g_QKV);
    cudaGetSymbolAddress((void**)&O,    g_O);
    cudaGetSymbolAddress((void**)&T,    g_T);
    cudaGetSymbolAddress((void**)&Hh,   g_Hh);
    cudaGetSymbolAddress((void**)&FF,   g_FF);

    // 1) fold wq/wk/wv -> one [1024,3072] weight
    repack_qkv<<<(Dn * 3 * Dn + 255) / 256, 256>>>(wq, wk, wv, bq, bk, bv);
    // 2) QKV projection: [8192,3072]
    tgemm<EPI_BIAS><<<dim3(3 * Dn / 128, Mn / 128), 256>>>(x, Wqkv, Bqkv, nullptr, QKV, Mn, 3 * Dn, Dn);
    // 3) causal flash attention -> O [B,S,D]
    attn_kernel<<<dim3(Sn / 128, Bn * Hn), 128>>>(QKV, O);
    // 4) O projection + residual x
    tgemm<EPI_RES><<<dim3(Dn / 128, Mn / 128), 256>>>(O, wo, bo, x, T, Mn, Dn, Dn);
    // 5) LayerNorm 1
    ln_kernel<<<Mn, 256>>>(T, g1, be1, Hh);
    // 6) FFN up + exact GELU
    tgemm<EPI_GELU><<<dim3(FFn / 128, Mn / 128), 256>>>(Hh, w1, b1, nullptr, FF, Mn, FFn, Dn);
    // 7) FFN down + residual h
    tgemm<EPI_RES><<<dim3(Dn / 128, Mn / 128), 256>>>(FF, w2, b2, Hh, T, Mn, Dn, FFn);
    // 8) LayerNorm 2 -> output
    ln_kernel<<<Mn, 256>>>(T, g2, be2, (float*)d_out);
}

// round 3
// speedup vs baseline: 3.3870x; 1.0913x over previous
#include <cuda_runtime.h>
#include <math.h>

// Problem constants
constexpr int Bn  = 4;
constexpr int Sn  = 2048;
constexpr int Dn  = 1024;
constexpr int Hn  = 16;
constexpr int HDn = 64;
constexpr int FFn = 4096;
constexpr int Mn  = Bn * Sn;        // 8192 rows
constexpr float NEG_INF = -1.0e30f;

// ---------------- scratch (static __device__, no allocations) ----------------
__device__ float g_Wqkv[Dn * 3 * Dn];   // [K=1024][N=3072] packed q|k|v
__device__ float g_Bqkv[3 * Dn];
__device__ float g_QKV [(size_t)Mn * 3 * Dn];  // [8192][3072] q|k|v per row
__device__ float g_O   [(size_t)Mn * Dn];      // attention output [B,S,D]
__device__ float g_T   [(size_t)Mn * Dn];      // residual temp
__device__ float g_Hh  [(size_t)Mn * Dn];      // post-LN1 hidden
__device__ float g_FF  [(size_t)Mn * FFn];     // FFN intermediate

// ---------------- weight repack: wq/wk/wv [H,D,HD] -> [D, 3*1024] ------------
__global__ void repack_qkv(const float* __restrict__ wq, const float* __restrict__ wk,
                           const float* __restrict__ wv, const float* __restrict__ bq,
                           const float* __restrict__ bk, const float* __restrict__ bv) {
    int gid = blockIdx.x * blockDim.x + threadIdx.x;
    const int total = Dn * 3 * Dn;
    if (gid < total) {
        int d     = gid / (3 * Dn);
        int col   = gid - d * (3 * Dn);
        int which = col >> 10;          // 0=q, 1=k, 2=v
        int c     = col & 1023;         // h*64 + f
        int h     = c >> 6, f = c & 63;
        const float* w = (which == 0) ? wq : (which == 1) ? wk : wv;
        g_Wqkv[gid] = w[((size_t)h * Dn + d) * HDn + f];
    }
    if (gid < 3 * Dn) {
        int which = gid >> 10; int c = gid & 1023;
        const float* b = (which == 0) ? bq : (which == 1) ? bk : bv;
        g_Bqkv[gid] = b[c];
    }
}

// ---------------- tf32 tensor-core GEMM 128x128x16 ---------------------------
// 128 threads = 4 warps in 2(m) x 2(n); warp tile 64x64 = 4x8 m16n8k8 tiles.
// A smem: m-major [128][20]  (stride 20 -> conflict-free A-fragment LDS)
// B smem: k-major [16][136]  (stride 136 -> conflict-free B-fragment LDS)
enum { EPI_BIAS = 0, EPI_GELU = 1, EPI_RES = 2 };

__device__ __forceinline__ float gelu_f(float x) {
    return 0.5f * x * (1.0f + erff(x * 0.70710678118654752440f));
}

__device__ __forceinline__ float4 cvt_tf32_4(float4 v) {
    asm("cvt.rna.tf32.f32 %0, %0;" : "+f"(v.x));
    asm("cvt.rna.tf32.f32 %0, %0;" : "+f"(v.y));
    asm("cvt.rna.tf32.f32 %0, %0;" : "+f"(v.z));
    asm("cvt.rna.tf32.f32 %0, %0;" : "+f"(v.w));
    return v;
}

__device__ __forceinline__ void mma_tf32(float* c, const float* a, const float* b) {
    asm volatile(
        "mma.sync.aligned.m16n8k8.row.col.f32.tf32.tf32.f32 "
        "{%0,%1,%2,%3}, {%4,%5,%6,%7}, {%8,%9}, {%0,%1,%2,%3};"
        : "+f"(c[0]), "+f"(c[1]), "+f"(c[2]), "+f"(c[3])
        : "r"(__float_as_uint(a[0])), "r"(__float_as_uint(a[1])),
          "r"(__float_as_uint(a[2])), "r"(__float_as_uint(a[3])),
          "r"(__float_as_uint(b[0])), "r"(__float_as_uint(b[1])));
}

constexpr int ASTR = 20;    // A smem row stride (floats)
constexpr int BSTR = 136;   // B smem row stride (floats)

template <int EPI>
__global__ void __launch_bounds__(128, 2)
tgemm(const float* __restrict__ A, const float* __restrict__ Bm,
      const float* __restrict__ bias, const float* __restrict__ Res,
      float* __restrict__ C, int M, int N, int K) {
    __shared__ float As[2][128 * ASTR];
    __shared__ float Bs[2][16 * BSTR];

    const int tid  = threadIdx.x;
    const int lane = tid & 31, wid = tid >> 5;      // 4 warps
    const int quad = lane >> 2, qt = lane & 3;
    const int wm = wid & 1, wn = wid >> 1;          // 2x2 warp grid
    const int m0 = blockIdx.y * 128, n0 = blockIdx.x * 128;

    // global load assignments (4 float4 each for A and B per k-tile)
    const int rA = tid >> 2;          // 0..31
    const int kA = (tid & 3) * 4;
    const int kB = tid >> 5;          // 0..3
    const int nB = (tid & 31) * 4;
    const float* Ag = A  + (size_t)(m0 + rA) * K + kA;
    const float* Bg = Bm + (size_t)kB * N + n0 + nB;

    float acc[4][8][4] = {};

    float4 av[4], bv[4];
    // prologue: LDG tile 0
    #pragma unroll
    for (int ld = 0; ld < 4; ld++) {
        av[ld] = *(const float4*)(Ag + (size_t)(ld * 32) * K);
        bv[ld] = *(const float4*)(Bg + (size_t)(ld * 4) * N);
    }

    const int aOff = rA * ASTR + kA;
    const int bOff = kB * BSTR + nB;

    // store tile 0 into buffer 0 (with tf32 rounding)
    #pragma unroll
    for (int ld = 0; ld < 4; ld++) {
        *(float4*)&As[0][aOff + ld * 32 * ASTR] = cvt_tf32_4(av[ld]);
        *(float4*)&Bs[0][bOff + ld * 4 * BSTR]  = cvt_tf32_4(bv[ld]);
    }
    __syncthreads();

    const int niter = K >> 4;
    int buf = 0;

    for (int it = 0; it < niter; it++) {
        // prefetch next tile into registers (overlaps with compute below)
        if (it + 1 < niter) {
            const float* An = Ag + (it + 1) * 16;
            const float* Bp = Bg + (size_t)(it + 1) * 16 * N;
            #pragma unroll
            for (int ld = 0; ld < 4; ld++) {
                av[ld] = *(const float4*)(An + (size_t)(ld * 32) * K);
                bv[ld] = *(const float4*)(Bp + (size_t)(ld * 4) * N);
            }
        }

        // compute on current buffer
        const float* Ab = As[buf];
        const float* Bb = Bs[buf];
        #pragma unroll
        for (int ks = 0; ks < 2; ks++) {
            const int kb = ks * 8;
            float af[4][4];
            float bf[8][2];
            #pragma unroll
            for (int mt = 0; mt < 4; mt++) {
                const float* p = Ab + (wm * 64 + mt * 16 + quad) * ASTR + kb + qt;
                af[mt][0] = p[0];
                af[mt][1] = p[8 * ASTR];
                af[mt][2] = p[4];
                af[mt][3] = p[8 * ASTR + 4];
            }
            #pragma unroll
            for (int nt = 0; nt < 8; nt++) {
                const float* p = Bb + (kb + qt) * BSTR + wn * 64 + nt * 8 + quad;
                bf[nt][0] = p[0];
                bf[nt][1] = p[4 * BSTR];
            }
            #pragma unroll
            for (int mt = 0; mt < 4; mt++)
                #pragma unroll
                for (int nt = 0; nt < 8; nt++)
                    mma_tf32(acc[mt][nt], af[mt], bf[nt]);
        }

        if (it + 1 < niter) {
            #pragma unroll
            for (int ld = 0; ld < 4; ld++) {
                *(float4*)&As[buf ^ 1][aOff + ld * 32 * ASTR] = cvt_tf32_4(av[ld]);
                *(float4*)&Bs[buf ^ 1][bOff + ld * 4 * BSTR]  = cvt_tf32_4(bv[ld]);
            }
            __syncthreads();
            buf ^= 1;
        }
    }

    // epilogue: each thread owns pairs (quad, qt*2..+1) in each 16x8 tile
    #pragma unroll
    for (int mt = 0; mt < 4; mt++) {
        const int r0 = m0 + wm * 64 + mt * 16 + quad;
        #pragma unroll
        for (int nt = 0; nt < 8; nt++) {
            const int col = n0 + wn * 64 + nt * 8 + qt * 2;
            const float2 bv2 = *(const float2*)&bias[col];
            #pragma unroll
            for (int half = 0; half < 2; half++) {
                const int r = r0 + half * 8;
                float2 y;
                y.x = acc[mt][nt][half * 2 + 0] + bv2.x;
                y.y = acc[mt][nt][half * 2 + 1] + bv2.y;
                size_t base = (size_t)r * N + col;
                if (EPI == EPI_GELU) {
                    y.x = gelu_f(y.x); y.y = gelu_f(y.y);
                } else if (EPI == EPI_RES) {
                    float2 rr = *(const float2*)&Res[base];
                    y.x += rr.x; y.y += rr.y;
                }
                *(float2*)&C[base] = y;
            }
        }
    }
}

// ---------------- causal flash attention, 1 query row per thread -------------
__global__ void __launch_bounds__(128, 2)
attn_kernel(const float* __restrict__ QKV, float* __restrict__ O) {
    __shared__ float Ks[64][64];
    __shared__ float Vs[64][64];

    const int t  = threadIdx.x;
    const int r0 = blockIdx.x * 128;
    const int bh = blockIdx.y;
    const int b  = bh >> 4, h = bh & 15;
    const int r  = r0 + t;                       // this thread's query row

    const float* qptr = QKV + ((size_t)(b * Sn + r)) * 3072 + h * 64;
    float q[64], o[64];
    #pragma unroll
    for (int d4 = 0; d4 < 16; d4++) {
        float4 v = *(const float4*)(qptr + d4 * 4);
        q[d4 * 4 + 0] = v.x * 0.125f;   // fold 1/sqrt(64)
        q[d4 * 4 + 1] = v.y * 0.125f;
        q[d4 * 4 + 2] = v.z * 0.125f;
        q[d4 * 4 + 3] = v.w * 0.125f;
    }
    #pragma unroll
    for (int d = 0; d < 64; d++) o[d] = 0.0f;
    float mrun = NEG_INF, lrun = 0.0f;

    const int ntiles = (r0 >> 6) + 2;            // keys up to r0+127
    for (int kt = 0; kt < ntiles; kt++) {
        const int base = kt * 64;
        const float* kg = QKV + ((size_t)(b * Sn + base)) * 3072 + 1024 + h * 64;
        const float* vg = kg + 1024;
        #pragma unroll
        for (int w = 0; w < 8; w++) {
            int idx = t + w * 128;               // 0..1023 float4 slots
            int j = idx >> 4, d4 = idx & 15;
            *(float4*)&Ks[j][d4 * 4] = *(const float4*)(kg + (size_t)j * 3072 + d4 * 4);
            *(float4*)&Vs[j][d4 * 4] = *(const float4*)(vg + (size_t)j * 3072 + d4 * 4);
        }
        __syncthreads();

        #pragma unroll 1
        for (int c = 0; c < 4; c++) {
            const int gk0 = base + c * 16;
            if (gk0 > r) break;                  // fully masked chunk

            float sarr[16];
            #pragma unroll
            for (int jj = 0; jj < 16; jj++) {
                const float4* kp = (const float4*)&Ks[c * 16 + jj][0];
                float s0 = 0.f, s1 = 0.f, s2 = 0.f, s3 = 0.f;
                #pragma unroll
                for (int dq = 0; dq < 4; dq++) {
                    float4 k0 = kp[dq * 4 + 0];
                    float4 k1 = kp[dq * 4 + 1];
                    float4 k2 = kp[dq * 4 + 2];
                    float4 k3 = kp[dq * 4 + 3];
                    const float* qq = &q[dq * 16];
                    s0 += qq[0]  * k0.x + qq[1]  * k0.y + qq[2]  * k0.z + qq[3]  * k0.w;
                    s1 += qq[4]  * k1.x + qq[5]  * k1.y + qq[6]  * k1.z + qq[7]  * k1.w;
                    s2 += qq[8]  * k2.x + qq[9]  * k2.y + qq[10] * k2.z + qq[11] * k2.w;
                    s3 += qq[12] * k3.x + qq[13] * k3.y + qq[14] * k3.z + qq[15] * k3.w;
                }
                sarr[jj] = (s0 + s1) + (s2 + s3);
            }
            #pragma unroll
            for (int jj = 0; jj < 16; jj++)
                if (gk0 + jj > r) sarr[jj] = NEG_INF;

            float cm = sarr[0];
            #pragma unroll
            for (int jj = 1; jj < 16; jj++) cm = fmaxf(cm, sarr[jj]);

            if (cm > mrun) {                     // rescale only when max moves
                float scale = __expf(mrun - cm); // mrun=-1e30 -> 0
                lrun *= scale;
                #pragma unroll
                for (int d = 0; d < 64; d++) o[d] *= scale;
                mrun = cm;
            }
            #pragma unroll
            for (int jj = 0; jj < 16; jj++) {
                float p = __expf(sarr[jj] - mrun);   // masked -> 0
                lrun += p;
                const float4* vp = (const float4*)&Vs[c * 16 + jj][0];
                #pragma unroll
                for (int d4 = 0; d4 < 16; d4++) {
                    float4 vv = vp[d4];
                    o[d4 * 4 + 0] += p * vv.x;
                    o[d4 * 4 + 1] += p * vv.y;
                    o[d4 * 4 + 2] += p * vv.z;
                    o[d4 * 4 + 3] += p * vv.w;
                }
            }
        }
        __syncthreads();
    }

    const float inv = 1.0f / lrun;
    float* optr = O + ((size_t)(b * Sn + r)) * Dn + h * 64;
    #pragma unroll
    for (int d4 = 0; d4 < 16; d4++) {
        float4 v;
        v.x = o[d4 * 4 + 0] * inv;
        v.y = o[d4 * 4 + 1] * inv;
        v.z = o[d4 * 4 + 2] * inv;
        v.w = o[d4 * 4 + 3] * inv;
        *(float4*)(optr + d4 * 4) = v;
    }
}

// ---------------- LayerNorm: one block per row of 1024 -----------------------
__global__ void __launch_bounds__(256)
ln_kernel(const float* __restrict__ X, const float* __restrict__ G,
          const float* __restrict__ Bt, float* __restrict__ Y) {
    const int row = blockIdx.x;
    const int t = threadIdx.x;
    const float* x = X + (size_t)row * Dn;

    float4 v = *(const float4*)(x + t * 4);
    float s  = v.x + v.y + v.z + v.w;
    float sq = v.x * v.x + v.y * v.y + v.z * v.z + v.w * v.w;
    #pragma unroll
    for (int off = 16; off; off >>= 1) {
        s  += __shfl_xor_sync(0xffffffffu, s,  off);
        sq += __shfl_xor_sync(0xffffffffu, sq, off);
    }
    __shared__ float rs[8], rq[8];
    int wid = t >> 5, lane = t & 31;
    if (lane == 0) { rs[wid] = s; rq[wid] = sq; }
    __syncthreads();
    if (t == 0) {
        float S = 0.f, Q = 0.f;
        #pragma unroll
        for (int i = 0; i < 8; i++) { S += rs[i]; Q += rq[i]; }
        float mean = S * (1.0f / Dn);
        float var  = Q * (1.0f / Dn) - mean * mean;
        rs[0] = mean;
        rq[0] = rsqrtf(var + 1e-5f);
    }
    __syncthreads();
    const float mean = rs[0], rstd = rq[0];

    float4 gv = *(const float4*)(G + t * 4);
    float4 bv = *(const float4*)(Bt + t * 4);
    float4 y;
    y.x = (v.x - mean) * rstd * gv.x + bv.x;
    y.y = (v.y - mean) * rstd * gv.y + bv.y;
    y.z = (v.z - mean) * rstd * gv.z + bv.z;
    y.w = (v.w - mean) * rstd * gv.w + bv.w;
    *(float4*)(Y + (size_t)row * Dn + t * 4) = y;
}

// ---------------- launch ----------------
extern "C" void kernel_launch(void* const* d_in, const int* in_sizes, int n_in,
                              void* d_out, int out_size) {
    const float* x   = (const float*)d_in[0];
    const float* wq  = (const float*)d_in[1];
    const float* bq  = (const float*)d_in[2];
    const float* wk  = (const float*)d_in[3];
    const float* bk  = (const float*)d_in[4];
    const float* wv  = (const float*)d_in[5];
    const float* bv  = (const float*)d_in[6];
    const float* wo  = (const float*)d_in[7];
    const float* bo  = (const float*)d_in[8];
    const float* w1  = (const float*)d_in[9];
    const float* b1  = (const float*)d_in[10];
    const float* w2  = (const float*)d_in[11];
    const float* b2  = (const float*)d_in[12];
    const float* g1  = (const float*)d_in[13];
    const float* be1 = (const float*)d_in[14];
    const float* g2  = (const float*)d_in[15];
    const float* be2 = (const float*)d_in[16];

    float *Wqkv, *Bqkv, *QKV, *O, *T, *Hh, *FF;
    cudaGetSymbolAddress((void**)&Wqkv, g_Wqkv);
    cudaGetSymbolAddress((void**)&Bqkv, g_Bqkv);
    cudaGetSymbolAddress((void**)&QKV,  g_QKV);
    cudaGetSymbolAddress((void**)&O,    g_O);
    cudaGetSymbolAddress((void**)&T,    g_T);
    cudaGetSymbolAddress((void**)&Hh,   g_Hh);
    cudaGetSymbolAddress((void**)&FF,   g_FF);

    // 1) fold wq/wk/wv -> one [1024,3072] weight
    repack_qkv<<<(Dn * 3 * Dn + 255) / 256, 256>>>(wq, wk, wv, bq, bk, bv);
    // 2) QKV projection: [8192,3072]
    tgemm<EPI_BIAS><<<dim3(3 * Dn / 128, Mn / 128), 128>>>(x, Wqkv, Bqkv, nullptr, QKV, Mn, 3 * Dn, Dn);
    // 3) causal flash attention -> O [B,S,D]
    attn_kernel<<<dim3(Sn / 128, Bn * Hn), 128>>>(QKV, O);
    // 4) O projection + residual x
    tgemm<EPI_RES><<<dim3(Dn / 128, Mn / 128), 128>>>(O, wo, bo, x, T, Mn, Dn, Dn);
    // 5) LayerNorm 1
    ln_kernel<<<Mn, 256>>>(T, g1, be1, Hh);
    // 6) FFN up + exact GELU
    tgemm<EPI_GELU><<<dim3(FFn / 128, Mn / 128), 128>>>(Hh, w1, b1, nullptr, FF, Mn, FFn, Dn);
    // 7) FFN down + residual h
    tgemm<EPI_RES><<<dim3(Dn / 128, Mn / 128), 128>>>(FF, w2, b2, Hh, T, Mn, Dn, FFn);
    // 8) LayerNorm 2 -> output
    ln_kernel<<<Mn, 256>>>(T, g2, be2, (float*)d_out);
}

// round 5
// speedup vs baseline: 4.2737x; 1.2618x over previous
#include <cuda_runtime.h>
#include <cuda_fp16.h>
#include <math.h>
#include <stdint.h>

// Problem constants
constexpr int Bn  = 4;
constexpr int Sn  = 2048;
constexpr int Dn  = 1024;
constexpr int HDn = 64;
constexpr int FFn = 4096;
constexpr int Mn  = Bn * Sn;        // 8192 rows
constexpr float NEG_INF = -1.0e30f;

// ---------------- scratch (static __device__, no allocations) ----------------
__device__ __half g_WqkvT[3 * Dn * Dn];        // [N=3072][K=1024] K-major, fp16
__device__ float  g_Bqkv [3 * Dn];
__device__ __half g_WoT  [Dn * Dn];            // [1024][1024]
__device__ __half g_W1T  [FFn * Dn];           // [4096][1024]
__device__ __half g_W2T  [Dn * FFn];           // [1024][4096]
__device__ __half g_xh  [(size_t)Mn * Dn];     // fp16 copy of x
__device__ float  g_QKV [(size_t)Mn * 3 * Dn]; // q|k|v per row (fp32)
__device__ __half g_Oh  [(size_t)Mn * Dn];     // attention out (fp16, GEMM input)
__device__ float  g_T   [(size_t)Mn * Dn];     // residual temp
__device__ float  g_Hh  [(size_t)Mn * Dn];     // post-LN1 hidden (fp32 residual)
__device__ __half g_Hhh [(size_t)Mn * Dn];     // post-LN1 hidden (fp16 GEMM input)
__device__ __half g_FFh [(size_t)Mn * FFn];    // FFN intermediate (fp16)

// ---------------- helpers ----------------
__device__ __forceinline__ uint32_t smem_u32(const void* p) {
    return (uint32_t)__cvta_generic_to_shared(p);
}
__device__ __forceinline__ void cpasync16(uint32_t dst, const void* src) {
    asm volatile("cp.async.ca.shared.global [%0], [%1], 16;" :: "r"(dst), "l"(src) : "memory");
}
__device__ __forceinline__ void cp_commit() {
    asm volatile("cp.async.commit_group;" ::: "memory");
}
__device__ __forceinline__ void mma_f16(float* c, const uint32_t* a, const uint32_t* b) {
    asm volatile(
        "mma.sync.aligned.m16n8k16.row.col.f32.f16.f16.f32 "
        "{%0,%1,%2,%3}, {%4,%5,%6,%7}, {%8,%9}, {%0,%1,%2,%3};"
        : "+f"(c[0]), "+f"(c[1]), "+f"(c[2]), "+f"(c[3])
        : "r"(a[0]), "r"(a[1]), "r"(a[2]), "r"(a[3]), "r"(b[0]), "r"(b[1]));
}

// ---------------- weight/activation repacks ----------------
__global__ void repack_qkvT(const float* __restrict__ wq, const float* __restrict__ wk,
                            const float* __restrict__ wv, const float* __restrict__ bq,
                            const float* __restrict__ bk, const float* __restrict__ bv) {
    int gid = blockIdx.x * blockDim.x + threadIdx.x;
    if (gid < 3 * Dn * Dn) {
        int n = gid >> 10;          // output row (N index)
        int d = gid & 1023;         // K index
        int which = n >> 10;
        int c = n & 1023;
        int h = c >> 6, f = c & 63;
        const float* w = (which == 0) ? wq : (which == 1) ? wk : wv;
        g_WqkvT[gid] = __float2half(w[((size_t)h * Dn + d) * HDn + f]);
    }
    if (gid < 3 * Dn) {
        int which = gid >> 10; int c = gid & 1023;
        const float* b = (which == 0) ? bq : (which == 1) ? bk : bv;
        g_Bqkv[gid] = b[c];
    }
}

// tiled transpose: dst[C][R] = src[R][C]^T, fp32 -> fp16
__global__ void transpose_kh(__half* __restrict__ dst, const float* __restrict__ src,
                             int R, int C) {
    __shared__ float tile[32][33];
    int c0 = blockIdx.x * 32, r0 = blockIdx.y * 32;
    int tx = threadIdx.x, ty = threadIdx.y;
    #pragma unroll
    for (int i = 0; i < 32; i += 8)
        tile[ty + i][tx] = src[(size_t)(r0 + ty + i) * C + c0 + tx];
    __syncthreads();
    #pragma unroll
    for (int i = 0; i < 32; i += 8)
        dst[(size_t)(c0 + ty + i) * R + r0 + tx] = __float2half(tile[tx][ty + i]);
}

// fp32 -> fp16 bulk convert
__global__ void f2h(const float* __restrict__ X, __half* __restrict__ Y, int n4) {
    int i = blockIdx.x * blockDim.x + threadIdx.x;
    if (i < n4) {
        float4 v = *(const float4*)(X + (size_t)i * 4);
        __half2 h0 = __floats2half2_rn(v.x, v.y);
        __half2 h1 = __floats2half2_rn(v.z, v.w);
        *(uint2*)(Y + (size_t)i * 4) = make_uint2(
            *(uint32_t*)&h0, *(uint32_t*)&h1);
    }
}

// ---------------- fp16 tensor GEMM 128x128x32, cp.async double buffer --------
// 128 threads = 4 warps (2m x 2n); warp tile 64x64 = 4x8 m16n8k16 tiles.
// SMEM: rows of 40 halves (80B) -> conflict-free 32-bit fragment LDS.
enum { EPI_BIAS = 0, EPI_GELUH = 1, EPI_RES = 2 };

__device__ __forceinline__ float gelu_f(float x) {
    return 0.5f * x * (1.0f + erff(x * 0.70710678118654752440f));
}

constexpr int ASTRH = 40;   // smem row stride in halves

template <int EPI>
__global__ void __launch_bounds__(128, 2)
hgemm(const __half* __restrict__ A, const __half* __restrict__ Bt,
      const float* __restrict__ bias, const float* __restrict__ Res,
      float* __restrict__ C, __half* __restrict__ Ch, int M, int N, int K) {
    __shared__ __half As[2][128 * ASTRH];
    __shared__ __half Bs[2][128 * ASTRH];

    const int tid  = threadIdx.x;
    const int lane = tid & 31, wid = tid >> 5;
    const int quad = lane >> 2, qt = lane & 3;
    const int wm = wid & 1, wn = wid >> 1;
    const int m0 = blockIdx.y * 128, n0 = blockIdx.x * 128;

    const uint32_t aS0 = smem_u32(As[0]), aS1 = smem_u32(As[1]);
    const uint32_t bS0 = smem_u32(Bs[0]), bS1 = smem_u32(Bs[1]);

    const int rL = tid >> 2;          // 0..31 base row (x4 chunks later)
    const int kc = (tid & 3) * 8;     // half offset within 32-half K chunk

    float acc[4][8][4] = {};

    auto load_tile = [&](int kt, int buf) {
        const uint32_t aB = (buf ? aS1 : aS0);
        const uint32_t bB = (buf ? bS1 : bS0);
        const __half* Ap = A  + (size_t)m0 * K + (size_t)kt * 32 + kc;
        const __half* Bp = Bt + (size_t)n0 * K + (size_t)kt * 32 + kc;
        #pragma unroll
        for (int i = 0; i < 4; i++) {
            int row = rL + i * 32;
            uint32_t off = row * (ASTRH * 2) + kc * 2;
            cpasync16(aB + off, Ap + (size_t)row * K);
            cpasync16(bB + off, Bp + (size_t)row * K);
        }
        cp_commit();
    };

    const int NT = K >> 5;
    load_tile(0, 0);

    for (int kt = 0; kt < NT; kt++) {
        const int buf = kt & 1;
        if (kt + 1 < NT) {
            load_tile(kt + 1, buf ^ 1);
            asm volatile("cp.async.wait_group 1;" ::: "memory");
        } else {
            asm volatile("cp.async.wait_group 0;" ::: "memory");
        }
        __syncthreads();

        const __half* Ab = As[buf];
        const __half* Bb = Bs[buf];
        #pragma unroll
        for (int ks = 0; ks < 2; ks++) {
            const int kb = ks * 16;
            uint32_t af[4][4], bf[8][2];
            #pragma unroll
            for (int mt = 0; mt < 4; mt++) {
                const __half* p = Ab + (wm * 64 + mt * 16 + quad) * ASTRH + kb + qt * 2;
                af[mt][0] = *(const uint32_t*)(p);
                af[mt][1] = *(const uint32_t*)(p + 8 * ASTRH);
                af[mt][2] = *(const uint32_t*)(p + 8);
                af[mt][3] = *(const uint32_t*)(p + 8 * ASTRH + 8);
            }
            #pragma unroll
            for (int nt = 0; nt < 8; nt++) {
                const __half* p = Bb + (wn * 64 + nt * 8 + quad) * ASTRH + kb + qt * 2;
                bf[nt][0] = *(const uint32_t*)(p);
                bf[nt][1] = *(const uint32_t*)(p + 8);
            }
            #pragma unroll
            for (int mt = 0; mt < 4; mt++)
                #pragma unroll
                for (int nt = 0; nt < 8; nt++)
                    mma_f16(acc[mt][nt], af[mt], bf[nt]);
        }
        __syncthreads();
    }

    // epilogue: thread owns (quad,+8 rows) x (qt*2,+1 cols) per 16x8 tile
    #pragma unroll
    for (int mt = 0; mt < 4; mt++) {
        const int r0 = m0 + wm * 64 + mt * 16 + quad;
        #pragma unroll
        for (int nt = 0; nt < 8; nt++) {
            const int col = n0 + wn * 64 + nt * 8 + qt * 2;
            const float2 bv2 = *(const float2*)&bias[col];
            #pragma unroll
            for (int half = 0; half < 2; half++) {
                const int r = r0 + half * 8;
                float2 y;
                y.x = acc[mt][nt][half * 2 + 0] + bv2.x;
                y.y = acc[mt][nt][half * 2 + 1] + bv2.y;
                size_t base = (size_t)r * N + col;
                if (EPI == EPI_GELUH) {
                    y.x = gelu_f(y.x); y.y = gelu_f(y.y);
                    __half2 h = __floats2half2_rn(y.x, y.y);
                    *(__half2*)&Ch[base] = h;
                } else if (EPI == EPI_RES) {
                    float2 rr = *(const float2*)&Res[base];
                    y.x += rr.x; y.y += rr.y;
                    *(float2*)&C[base] = y;
                } else {
                    *(float2*)&C[base] = y;
                }
            }
        }
    }
}

// ---------------- causal flash attention, 1 query row per thread -------------
__global__ void __launch_bounds__(128, 2)
attn_kernel(const float* __restrict__ QKV, __half* __restrict__ O) {
    __shared__ float Ks[64][64];
    __shared__ float Vs[64][64];

    const int t  = threadIdx.x;
    const int r0 = blockIdx.x * 128;
    const int bh = blockIdx.y;
    const int b  = bh >> 4, h = bh & 15;
    const int r  = r0 + t;

    const float* qptr = QKV + ((size_t)(b * Sn + r)) * 3072 + h * 64;
    float q[64], o[64];
    #pragma unroll
    for (int d4 = 0; d4 < 16; d4++) {
        float4 v = *(const float4*)(qptr + d4 * 4);
        q[d4 * 4 + 0] = v.x * 0.125f;
        q[d4 * 4 + 1] = v.y * 0.125f;
        q[d4 * 4 + 2] = v.z * 0.125f;
        q[d4 * 4 + 3] = v.w * 0.125f;
    }
    #pragma unroll
    for (int d = 0; d < 64; d++) o[d] = 0.0f;
    float mrun = NEG_INF, lrun = 0.0f;

    const int ntiles = (r0 >> 6) + 2;
    for (int kt = 0; kt < ntiles; kt++) {
        const int base = kt * 64;
        const float* kg = QKV + ((size_t)(b * Sn + base)) * 3072 + 1024 + h * 64;
        const float* vg = kg + 1024;
        #pragma unroll
        for (int w = 0; w < 8; w++) {
            int idx = t + w * 128;
            int j = idx >> 4, d4 = idx & 15;
            *(float4*)&Ks[j][d4 * 4] = *(const float4*)(kg + (size_t)j * 3072 + d4 * 4);
            *(float4*)&Vs[j][d4 * 4] = *(const float4*)(vg + (size_t)j * 3072 + d4 * 4);
        }
        __syncthreads();

        #pragma unroll 1
        for (int c = 0; c < 4; c++) {
            const int gk0 = base + c * 16;
            if (gk0 > r) break;

            float sarr[16];
            #pragma unroll
            for (int jj = 0; jj < 16; jj++) {
                const float4* kp = (const float4*)&Ks[c * 16 + jj][0];
                float s0 = 0.f, s1 = 0.f, s2 = 0.f, s3 = 0.f;
                #pragma unroll
                for (int dq = 0; dq < 4; dq++) {
                    float4 k0 = kp[dq * 4 + 0];
                    float4 k1 = kp[dq * 4 + 1];
                    float4 k2 = kp[dq * 4 + 2];
                    float4 k3 = kp[dq * 4 + 3];
                    const float* qq = &q[dq * 16];
                    s0 += qq[0]  * k0.x + qq[1]  * k0.y + qq[2]  * k0.z + qq[3]  * k0.w;
                    s1 += qq[4]  * k1.x + qq[5]  * k1.y + qq[6]  * k1.z + qq[7]  * k1.w;
                    s2 += qq[8]  * k2.x + qq[9]  * k2.y + qq[10] * k2.z + qq[11] * k2.w;
                    s3 += qq[12] * k3.x + qq[13] * k3.y + qq[14] * k3.z + qq[15] * k3.w;
                }
                sarr[jj] = (s0 + s1) + (s2 + s3);
            }
            #pragma unroll
            for (int jj = 0; jj < 16; jj++)
                if (gk0 + jj > r) sarr[jj] = NEG_INF;

            float cm = sarr[0];
            #pragma unroll
            for (int jj = 1; jj < 16; jj++) cm = fmaxf(cm, sarr[jj]);

            if (cm > mrun) {
                float scale = __expf(mrun - cm);
                lrun *= scale;
                #pragma unroll
                for (int d = 0; d < 64; d++) o[d] *= scale;
                mrun = cm;
            }
            #pragma unroll
            for (int jj = 0; jj < 16; jj++) {
                float p = __expf(sarr[jj] - mrun);
                lrun += p;
                const float4* vp = (const float4*)&Vs[c * 16 + jj][0];
                #pragma unroll
                for (int d4 = 0; d4 < 16; d4++) {
                    float4 vv = vp[d4];
                    o[d4 * 4 + 0] += p * vv.x;
                    o[d4 * 4 + 1] += p * vv.y;
                    o[d4 * 4 + 2] += p * vv.z;
                    o[d4 * 4 + 3] += p * vv.w;
                }
            }
        }
        __syncthreads();
    }

    const float inv = 1.0f / lrun;
    __half* optr = O + ((size_t)(b * Sn + r)) * Dn + h * 64;
    #pragma unroll
    for (int d2 = 0; d2 < 32; d2++) {
        __half2 hv = __floats2half2_rn(o[d2 * 2] * inv, o[d2 * 2 + 1] * inv);
        *(__half2*)(optr + d2 * 2) = hv;
    }
}

// ---------------- LayerNorm: one block per row of 1024 -----------------------
__global__ void __launch_bounds__(256)
ln_kernel(const float* __restrict__ X, const float* __restrict__ G,
          const float* __restrict__ Bt, float* __restrict__ Y,
          __half* __restrict__ Yh) {
    const int row = blockIdx.x;
    const int t = threadIdx.x;
    const float* x = X + (size_t)row * Dn;

    float4 v = *(const float4*)(x + t * 4);
    float s  = v.x + v.y + v.z + v.w;
    float sq = v.x * v.x + v.y * v.y + v.z * v.z + v.w * v.w;
    #pragma unroll
    for (int off = 16; off; off >>= 1) {
        s  += __shfl_xor_sync(0xffffffffu, s,  off);
        sq += __shfl_xor_sync(0xffffffffu, sq, off);
    }
    __shared__ float rs[8], rq[8];
    int wid = t >> 5, lane = t & 31;
    if (lane == 0) { rs[wid] = s; rq[wid] = sq; }
    __syncthreads();
    if (t == 0) {
        float S = 0.f, Q = 0.f;
        #pragma unroll
        for (int i = 0; i < 8; i++) { S += rs[i]; Q += rq[i]; }
        float mean = S * (1.0f / Dn);
        float var  = Q * (1.0f / Dn) - mean * mean;
        rs[0] = mean;
        rq[0] = rsqrtf(var + 1e-5f);
    }
    __syncthreads();
    const float mean = rs[0], rstd = rq[0];

    float4 gv = *(const float4*)(G + t * 4);
    float4 bv = *(const float4*)(Bt + t * 4);
    float4 y;
    y.x = (v.x - mean) * rstd * gv.x + bv.x;
    y.y = (v.y - mean) * rstd * gv.y + bv.y;
    y.z = (v.z - mean) * rstd * gv.z + bv.z;
    y.w = (v.w - mean) * rstd * gv.w + bv.w;
    *(float4*)(Y + (size_t)row * Dn + t * 4) = y;
    if (Yh) {
        __half2 h0 = __floats2half2_rn(y.x, y.y);
        __half2 h1 = __floats2half2_rn(y.z, y.w);
        *(uint2*)(Yh + (size_t)row * Dn + t * 4) =
            make_uint2(*(uint32_t*)&h0, *(uint32_t*)&h1);
    }
}

// ---------------- launch ----------------
extern "C" void kernel_launch(void* const* d_in, const int* in_sizes, int n_in,
                              void* d_out, int out_size) {
    const float* x   = (const float*)d_in[0];
    const float* wq  = (const float*)d_in[1];
    const float* bq  = (const float*)d_in[2];
    const float* wk  = (const float*)d_in[3];
    const float* bk  = (const float*)d_in[4];
    const float* wv  = (const float*)d_in[5];
    const float* bv  = (const float*)d_in[6];
    const float* wo  = (const float*)d_in[7];
    const float* bo  = (const float*)d_in[8];
    const float* w1  = (const float*)d_in[9];
    const float* b1  = (const float*)d_in[10];
    const float* w2  = (const float*)d_in[11];
    const float* b2  = (const float*)d_in[12];
    const float* g1  = (const float*)d_in[13];
    const float* be1 = (const float*)d_in[14];
    const float* g2  = (const float*)d_in[15];
    const float* be2 = (const float*)d_in[16];

    __half *WqkvT, *WoT, *W1T, *W2T, *xh, *Oh, *Hhh, *FFh;
    float *Bqkv, *QKV, *T, *Hh;
    cudaGetSymbolAddress((void**)&WqkvT, g_WqkvT);
    cudaGetSymbolAddress((void**)&Bqkv,  g_Bqkv);
    cudaGetSymbolAddress((void**)&WoT,   g_WoT);
    cudaGetSymbolAddress((void**)&W1T,   g_W1T);
    cudaGetSymbolAddress((void**)&W2T,   g_W2T);
    cudaGetSymbolAddress((void**)&xh,    g_xh);
    cudaGetSymbolAddress((void**)&QKV,   g_QKV);
    cudaGetSymbolAddress((void**)&Oh,    g_Oh);
    cudaGetSymbolAddress((void**)&T,     g_T);
    cudaGetSymbolAddress((void**)&Hh,    g_Hh);
    cudaGetSymbolAddress((void**)&Hhh,   g_Hhh);
    cudaGetSymbolAddress((void**)&FFh,   g_FFh);

    // 0) weight repacks ([N][K] K-major fp16) + x -> fp16
    repack_qkvT<<<(3 * Dn * Dn + 255) / 256, 256>>>(wq, wk, wv, bq, bk, bv);
    transpose_kh<<<dim3(Dn / 32, Dn / 32),  dim3(32, 8)>>>(WoT, wo, Dn, Dn);
    transpose_kh<<<dim3(FFn / 32, Dn / 32), dim3(32, 8)>>>(W1T, w1, Dn, FFn);
    transpose_kh<<<dim3(Dn / 32, FFn / 32), dim3(32, 8)>>>(W2T, w2, FFn, Dn);
    f2h<<<(Mn * Dn / 4 + 255) / 256, 256>>>(x, xh, Mn * Dn / 4);

    // 1) QKV projection (fp32 out for attention)
    hgemm<EPI_BIAS><<<dim3(3 * Dn / 128, Mn / 128), 128>>>(
        xh, WqkvT, Bqkv, nullptr, QKV, nullptr, Mn, 3 * Dn, Dn);
    // 2) causal flash attention -> Oh (fp16)
    attn_kernel<<<dim3(Sn / 128, Bn * 16), 128>>>(QKV, Oh);
    // 3) O projection + residual x
    hgemm<EPI_RES><<<dim3(Dn / 128, Mn / 128), 128>>>(
        Oh, WoT, bo, x, T, nullptr, Mn, Dn, Dn);
    // 4) LayerNorm 1 (fp32 + fp16 twin)
    ln_kernel<<<Mn, 256>>>(T, g1, be1, Hh, Hhh);
    // 5) FFN up + exact GELU -> fp16
    hgemm<EPI_GELUH><<<dim3(FFn / 128, Mn / 128), 128>>>(
        Hhh, W1T, b1, nullptr, nullptr, FFh, Mn, FFn, Dn);
    // 6) FFN down + residual Hh
    hgemm<EPI_RES><<<dim3(Dn / 128, Mn / 128), 128>>>(
        FFh, W2T, b2, Hh, T, nullptr, Mn, Dn, FFn);
    // 7) LayerNorm 2 -> output
    ln_kernel<<<Mn, 256>>>(T, g2, be2, (float*)d_out, nullptr);
}

// round 6
// speedup vs baseline: 9.8591x; 2.3069x over previous
#include <cuda_runtime.h>
#include <cuda_fp16.h>
#include <math.h>
#include <stdint.h>

// Problem constants
constexpr int Bn  = 4;
constexpr int Sn  = 2048;
constexpr int Dn  = 1024;
constexpr int HDn = 64;
constexpr int FFn = 4096;
constexpr int Mn  = Bn * Sn;        // 8192 rows
constexpr float NEG_INF = -1.0e30f;

// ---------------- scratch (static __device__, no allocations) ----------------
__device__ __half g_WqkvT[3 * Dn * Dn];        // [N=3072][K=1024] K-major, fp16
__device__ float  g_Bqkv [3 * Dn];
__device__ __half g_WoT  [Dn * Dn];
__device__ __half g_W1T  [FFn * Dn];
__device__ __half g_W2T  [Dn * FFn];
__device__ __half g_xh  [(size_t)Mn * Dn];     // fp16 copy of x
__device__ __half g_QKVh[(size_t)Mn * 3 * Dn]; // q|k|v per row (fp16)
__device__ __half g_Vth [(size_t)64 * HDn * Sn]; // V transposed: [bh][hd][s]
__device__ __half g_Oh  [(size_t)Mn * Dn];     // attention out (fp16)
__device__ float  g_T   [(size_t)Mn * Dn];     // residual temp
__device__ float  g_Hh  [(size_t)Mn * Dn];     // post-LN1 hidden (fp32)
__device__ __half g_Hhh [(size_t)Mn * Dn];     // post-LN1 hidden (fp16)
__device__ __half g_FFh [(size_t)Mn * FFn];    // FFN intermediate (fp16)

// ---------------- helpers ----------------
__device__ __forceinline__ uint32_t smem_u32(const void* p) {
    return (uint32_t)__cvta_generic_to_shared(p);
}
__device__ __forceinline__ void cpasync16(uint32_t dst, const void* src) {
    asm volatile("cp.async.ca.shared.global [%0], [%1], 16;" :: "r"(dst), "l"(src) : "memory");
}
__device__ __forceinline__ void cp_commit() {
    asm volatile("cp.async.commit_group;" ::: "memory");
}
__device__ __forceinline__ void mma_f16(float* c, const uint32_t* a, const uint32_t* b) {
    asm volatile(
        "mma.sync.aligned.m16n8k16.row.col.f32.f16.f16.f32 "
        "{%0,%1,%2,%3}, {%4,%5,%6,%7}, {%8,%9}, {%0,%1,%2,%3};"
        : "+f"(c[0]), "+f"(c[1]), "+f"(c[2]), "+f"(c[3])
        : "r"(a[0]), "r"(a[1]), "r"(a[2]), "r"(a[3]), "r"(b[0]), "r"(b[1]));
}

// ---------------- weight/activation repacks ----------------
__global__ void repack_qkvT(const float* __restrict__ wq, const float* __restrict__ wk,
                            const float* __restrict__ wv, const float* __restrict__ bq,
                            const float* __restrict__ bk, const float* __restrict__ bv) {
    int gid = blockIdx.x * blockDim.x + threadIdx.x;
    if (gid < 3 * Dn * Dn) {
        int n = gid >> 10;
        int d = gid & 1023;
        int which = n >> 10;
        int c = n & 1023;
        int h = c >> 6, f = c & 63;
        const float* w = (which == 0) ? wq : (which == 1) ? wk : wv;
        g_WqkvT[gid] = __float2half(w[((size_t)h * Dn + d) * HDn + f]);
    }
    if (gid < 3 * Dn) {
        int which = gid >> 10; int c = gid & 1023;
        const float* b = (which == 0) ? bq : (which == 1) ? bk : bv;
        g_Bqkv[gid] = b[c];
    }
}

__global__ void transpose_kh(__half* __restrict__ dst, const float* __restrict__ src,
                             int R, int C) {
    __shared__ float tile[32][33];
    int c0 = blockIdx.x * 32, r0 = blockIdx.y * 32;
    int tx = threadIdx.x, ty = threadIdx.y;
    #pragma unroll
    for (int i = 0; i < 32; i += 8)
        tile[ty + i][tx] = src[(size_t)(r0 + ty + i) * C + c0 + tx];
    __syncthreads();
    #pragma unroll
    for (int i = 0; i < 32; i += 8)
        dst[(size_t)(c0 + ty + i) * R + r0 + tx] = __float2half(tile[tx][ty + i]);
}

__global__ void f2h(const float* __restrict__ X, __half* __restrict__ Y, int n4) {
    int i = blockIdx.x * blockDim.x + threadIdx.x;
    if (i < n4) {
        float4 v = *(const float4*)(X + (size_t)i * 4);
        __half2 h0 = __floats2half2_rn(v.x, v.y);
        __half2 h1 = __floats2half2_rn(v.z, v.w);
        *(uint2*)(Y + (size_t)i * 4) = make_uint2(*(uint32_t*)&h0, *(uint32_t*)&h1);
    }
}

// V per-head transpose: Vth[(bh*64 + f)*S + s] = QKVh[(b*S+s)*3072 + 2048 + h*64 + f]
__global__ void vtrans(const __half* __restrict__ QKVh, __half* __restrict__ Vth) {
    __shared__ __half tile[32][33];
    int bh = blockIdx.z, b = bh >> 4, h = bh & 15;
    int s0 = blockIdx.x * 32, f0 = blockIdx.y * 32;
    int tx = threadIdx.x, ty = threadIdx.y;
    #pragma unroll
    for (int i = 0; i < 32; i += 8)
        tile[ty + i][tx] = QKVh[(size_t)(b * Sn + s0 + ty + i) * 3072 + 2048 + h * 64 + f0 + tx];
    __syncthreads();
    #pragma unroll
    for (int i = 0; i < 32; i += 8)
        Vth[((size_t)bh * 64 + f0 + ty + i) * Sn + s0 + tx] = tile[tx][ty + i];
}

// ---------------- fp16 tensor GEMM 128x128x32, cp.async double buffer --------
enum { EPI_BIAS = 0, EPI_GELUH = 1, EPI_RES = 2, EPI_BIASH = 3 };

__device__ __forceinline__ float gelu_f(float x) {
    return 0.5f * x * (1.0f + erff(x * 0.70710678118654752440f));
}

constexpr int ASTRH = 40;   // smem row stride in halves

template <int EPI>
__global__ void __launch_bounds__(128, 2)
hgemm(const __half* __restrict__ A, const __half* __restrict__ Bt,
      const float* __restrict__ bias, const float* __restrict__ Res,
      float* __restrict__ C, __half* __restrict__ Ch, int M, int N, int K) {
    __shared__ __half As[2][128 * ASTRH];
    __shared__ __half Bs[2][128 * ASTRH];

    const int tid  = threadIdx.x;
    const int lane = tid & 31, wid = tid >> 5;
    const int quad = lane >> 2, qt = lane & 3;
    const int wm = wid & 1, wn = wid >> 1;
    const int m0 = blockIdx.y * 128, n0 = blockIdx.x * 128;

    const uint32_t aS0 = smem_u32(As[0]), aS1 = smem_u32(As[1]);
    const uint32_t bS0 = smem_u32(Bs[0]), bS1 = smem_u32(Bs[1]);

    const int rL = tid >> 2;
    const int kc = (tid & 3) * 8;

    float acc[4][8][4] = {};

    auto load_tile = [&](int kt, int buf) {
        const uint32_t aB = (buf ? aS1 : aS0);
        const uint32_t bB = (buf ? bS1 : bS0);
        const __half* Ap = A  + (size_t)m0 * K + (size_t)kt * 32 + kc;
        const __half* Bp = Bt + (size_t)n0 * K + (size_t)kt * 32 + kc;
        #pragma unroll
        for (int i = 0; i < 4; i++) {
            int row = rL + i * 32;
            uint32_t off = row * (ASTRH * 2) + kc * 2;
            cpasync16(aB + off, Ap + (size_t)row * K);
            cpasync16(bB + off, Bp + (size_t)row * K);
        }
        cp_commit();
    };

    const int NT = K >> 5;
    load_tile(0, 0);

    for (int kt = 0; kt < NT; kt++) {
        const int buf = kt & 1;
        if (kt + 1 < NT) {
            load_tile(kt + 1, buf ^ 1);
            asm volatile("cp.async.wait_group 1;" ::: "memory");
        } else {
            asm volatile("cp.async.wait_group 0;" ::: "memory");
        }
        __syncthreads();

        const __half* Ab = As[buf];
        const __half* Bb = Bs[buf];
        #pragma unroll
        for (int ks = 0; ks < 2; ks++) {
            const int kb = ks * 16;
            uint32_t af[4][4], bf[8][2];
            #pragma unroll
            for (int mt = 0; mt < 4; mt++) {
                const __half* p = Ab + (wm * 64 + mt * 16 + quad) * ASTRH + kb + qt * 2;
                af[mt][0] = *(const uint32_t*)(p);
                af[mt][1] = *(const uint32_t*)(p + 8 * ASTRH);
                af[mt][2] = *(const uint32_t*)(p + 8);
                af[mt][3] = *(const uint32_t*)(p + 8 * ASTRH + 8);
            }
            #pragma unroll
            for (int nt = 0; nt < 8; nt++) {
                const __half* p = Bb + (wn * 64 + nt * 8 + quad) * ASTRH + kb + qt * 2;
                bf[nt][0] = *(const uint32_t*)(p);
                bf[nt][1] = *(const uint32_t*)(p + 8);
            }
            #pragma unroll
            for (int mt = 0; mt < 4; mt++)
                #pragma unroll
                for (int nt = 0; nt < 8; nt++)
                    mma_f16(acc[mt][nt], af[mt], bf[nt]);
        }
        __syncthreads();
    }

    #pragma unroll
    for (int mt = 0; mt < 4; mt++) {
        const int r0 = m0 + wm * 64 + mt * 16 + quad;
        #pragma unroll
        for (int nt = 0; nt < 8; nt++) {
            const int col = n0 + wn * 64 + nt * 8 + qt * 2;
            const float2 bv2 = *(const float2*)&bias[col];
            #pragma unroll
            for (int half = 0; half < 2; half++) {
                const int r = r0 + half * 8;
                float2 y;
                y.x = acc[mt][nt][half * 2 + 0] + bv2.x;
                y.y = acc[mt][nt][half * 2 + 1] + bv2.y;
                size_t base = (size_t)r * N + col;
                if (EPI == EPI_GELUH) {
                    y.x = gelu_f(y.x); y.y = gelu_f(y.y);
                    __half2 hh = __floats2half2_rn(y.x, y.y);
                    *(__half2*)&Ch[base] = hh;
                } else if (EPI == EPI_BIASH) {
                    __half2 hh = __floats2half2_rn(y.x, y.y);
                    *(__half2*)&Ch[base] = hh;
                } else if (EPI == EPI_RES) {
                    float2 rr = *(const float2*)&Res[base];
                    y.x += rr.x; y.y += rr.y;
                    *(float2*)&C[base] = y;
                } else {
                    *(float2*)&C[base] = y;
                }
            }
        }
    }
}

// ---------------- tensor-core causal flash attention -------------------------
// CTA: 64 query rows x one (b,h); 4 warps x 16 rows. K/V tiles of 64 keys,
// double-buffered cp.async. S and O accumulate in fp32 fragments.
constexpr int FSTR = 72;   // smem stride (halves): bank = 4*(lane>>2)+(lane&3)

__global__ void __launch_bounds__(128)
fattn(const __half* __restrict__ QKVh, const __half* __restrict__ Vth,
      __half* __restrict__ O) {
    __shared__ __half Qs[64][FSTR];
    __shared__ __half Ks[2][64][FSTR];
    __shared__ __half Vs[2][64][FSTR];   // [hd][key]

    const int tid = threadIdx.x;
    const int lane = tid & 31, wid = tid >> 5;
    const int q4 = lane >> 2, qt2 = (lane & 3) * 2;
    const int qtile = blockIdx.x;            // 0..31
    const int bh = blockIdx.y, b = bh >> 4, h = bh & 15;
    const int r0 = qtile * 64;

    const uint32_t qB = smem_u32(&Qs[0][0]);
    const uint32_t kB0 = smem_u32(&Ks[0][0][0]), kB1 = smem_u32(&Ks[1][0][0]);
    const uint32_t vB0 = smem_u32(&Vs[0][0][0]), vB1 = smem_u32(&Vs[1][0][0]);

    const int ldr = tid >> 3;           // 0..15 base row for loads
    const int ldc = (tid & 7) * 8;      // half offset

    // load Q tile (64 rows x 64 halves)
    {
        const __half* Qg = QKVh + ((size_t)(b * Sn + r0)) * 3072 + h * 64;
        #pragma unroll
        for (int i = 0; i < 4; i++) {
            int row = ldr + i * 16;
            cpasync16(qB + (row * FSTR + ldc) * 2, Qg + (size_t)row * 3072 + ldc);
        }
        cp_commit();
    }

    auto loadKV = [&](int kt, int buf) {
        const __half* Kg = QKVh + ((size_t)(b * Sn + kt * 64)) * 3072 + 1024 + h * 64;
        const __half* Vg = Vth + ((size_t)bh * 64) * Sn + kt * 64;
        const uint32_t kB = buf ? kB1 : kB0;
        const uint32_t vB = buf ? vB1 : vB0;
        #pragma unroll
        for (int i = 0; i < 4; i++) {
            int row = ldr + i * 16;
            cpasync16(kB + (row * FSTR + ldc) * 2, Kg + (size_t)row * 3072 + ldc);
            cpasync16(vB + (row * FSTR + ldc) * 2, Vg + (size_t)row * Sn + ldc);
        }
        cp_commit();
    };

    loadKV(0, 0);

    // extract Q fragments (kept in registers for whole kernel)
    asm volatile("cp.async.wait_group 1;" ::: "memory");   // Q done
    __syncthreads();
    uint32_t aQ[4][4];
    {
        const __half* p0 = &Qs[wid * 16 + q4][qt2];
        #pragma unroll
        for (int kcc = 0; kcc < 4; kcc++) {
            const __half* p = p0 + kcc * 16;
            aQ[kcc][0] = *(const uint32_t*)(p);
            aQ[kcc][1] = *(const uint32_t*)(p + 8 * FSTR);
            aQ[kcc][2] = *(const uint32_t*)(p + 8);
            aQ[kcc][3] = *(const uint32_t*)(p + 8 * FSTR + 8);
        }
    }

    const int rowg0 = r0 + wid * 16 + q4;     // this thread's row (e0,e1)
    const int rowg1 = rowg0 + 8;              // (e2,e3)

    float m0 = NEG_INF, m1 = NEG_INF, l0 = 0.f, l1 = 0.f;
    float o[8][4] = {};

    for (int kt = 0; kt <= qtile; kt++) {
        const int buf = kt & 1;
        if (kt < qtile) {
            loadKV(kt + 1, buf ^ 1);
            asm volatile("cp.async.wait_group 1;" ::: "memory");
        } else {
            asm volatile("cp.async.wait_group 0;" ::: "memory");
        }
        __syncthreads();

        // S = Q @ K^T  (8 key tiles of 8)
        float s[8][4] = {};
        #pragma unroll
        for (int kcc = 0; kcc < 4; kcc++) {
            #pragma unroll
            for (int nt = 0; nt < 8; nt++) {
                const __half* p = &Ks[buf][nt * 8 + q4][kcc * 16 + qt2];
                uint32_t bb[2] = { *(const uint32_t*)(p), *(const uint32_t*)(p + 8) };
                mma_f16(s[nt], aQ[kcc], bb);
            }
        }

        // scale + causal mask + row max
        const int colb = kt * 64 + qt2;
        float mx0 = NEG_INF, mx1 = NEG_INF;
        #pragma unroll
        for (int nt = 0; nt < 8; nt++) {
            const int c0 = colb + nt * 8;
            s[nt][0] = (c0     <= rowg0) ? s[nt][0] * 0.125f : NEG_INF;
            s[nt][1] = (c0 + 1 <= rowg0) ? s[nt][1] * 0.125f : NEG_INF;
            s[nt][2] = (c0     <= rowg1) ? s[nt][2] * 0.125f : NEG_INF;
            s[nt][3] = (c0 + 1 <= rowg1) ? s[nt][3] * 0.125f : NEG_INF;
            mx0 = fmaxf(mx0, fmaxf(s[nt][0], s[nt][1]));
            mx1 = fmaxf(mx1, fmaxf(s[nt][2], s[nt][3]));
        }
        mx0 = fmaxf(mx0, __shfl_xor_sync(0xffffffffu, mx0, 1));
        mx0 = fmaxf(mx0, __shfl_xor_sync(0xffffffffu, mx0, 2));
        mx1 = fmaxf(mx1, __shfl_xor_sync(0xffffffffu, mx1, 1));
        mx1 = fmaxf(mx1, __shfl_xor_sync(0xffffffffu, mx1, 2));

        const float mn0 = fmaxf(m0, mx0), mn1 = fmaxf(m1, mx1);
        const float sc0 = __expf(m0 - mn0), sc1 = __expf(m1 - mn1);
        m0 = mn0; m1 = mn1;

        float rs0 = 0.f, rs1 = 0.f;
        uint32_t pf[4][4];
        #pragma unroll
        for (int nt = 0; nt < 8; nt++) {
            float p0 = __expf(s[nt][0] - m0);
            float p1 = __expf(s[nt][1] - m0);
            float p2 = __expf(s[nt][2] - m1);
            float p3 = __expf(s[nt][3] - m1);
            rs0 += p0 + p1; rs1 += p2 + p3;
            __half2 h01 = __floats2half2_rn(p0, p1);
            __half2 h23 = __floats2half2_rn(p2, p3);
            pf[nt >> 1][(nt & 1) * 2 + 0] = *(uint32_t*)&h01;
            pf[nt >> 1][(nt & 1) * 2 + 1] = *(uint32_t*)&h23;
        }
        rs0 += __shfl_xor_sync(0xffffffffu, rs0, 1);
        rs0 += __shfl_xor_sync(0xffffffffu, rs0, 2);
        rs1 += __shfl_xor_sync(0xffffffffu, rs1, 1);
        rs1 += __shfl_xor_sync(0xffffffffu, rs1, 2);
        l0 = l0 * sc0 + rs0;
        l1 = l1 * sc1 + rs1;

        #pragma unroll
        for (int nt = 0; nt < 8; nt++) {
            o[nt][0] *= sc0; o[nt][1] *= sc0;
            o[nt][2] *= sc1; o[nt][3] *= sc1;
        }

        // O += P @ V   (keys = k dim, hd = n dim; Vs is [hd][key])
        #pragma unroll
        for (int kcc = 0; kcc < 4; kcc++) {
            #pragma unroll
            for (int nt = 0; nt < 8; nt++) {
                const __half* p = &Vs[buf][nt * 8 + q4][kcc * 16 + qt2];
                uint32_t bb[2] = { *(const uint32_t*)(p), *(const uint32_t*)(p + 8) };
                mma_f16(o[nt], pf[kcc], bb);
            }
        }
        __syncthreads();
    }

    const float li0 = 1.0f / l0, li1 = 1.0f / l1;
    __half* Op0 = O + ((size_t)(b * Sn + rowg0)) * Dn + h * 64 + qt2;
    __half* Op1 = O + ((size_t)(b * Sn + rowg1)) * Dn + h * 64 + qt2;
    #pragma unroll
    for (int nt = 0; nt < 8; nt++) {
        __half2 h0 = __floats2half2_rn(o[nt][0] * li0, o[nt][1] * li0);
        __half2 h1 = __floats2half2_rn(o[nt][2] * li1, o[nt][3] * li1);
        *(__half2*)(Op0 + nt * 8) = h0;
        *(__half2*)(Op1 + nt * 8) = h1;
    }
}

// ---------------- LayerNorm: one block per row of 1024 -----------------------
__global__ void __launch_bounds__(256)
ln_kernel(const float* __restrict__ X, const float* __restrict__ G,
          const float* __restrict__ Bt, float* __restrict__ Y,
          __half* __restrict__ Yh) {
    const int row = blockIdx.x;
    const int t = threadIdx.x;
    const float* x = X + (size_t)row * Dn;

    float4 v = *(const float4*)(x + t * 4);
    float s  = v.x + v.y + v.z + v.w;
    float sq = v.x * v.x + v.y * v.y + v.z * v.z + v.w * v.w;
    #pragma unroll
    for (int off = 16; off; off >>= 1) {
        s  += __shfl_xor_sync(0xffffffffu, s,  off);
        sq += __shfl_xor_sync(0xffffffffu, sq, off);
    }
    __shared__ float rs[8], rq[8];
    int wid = t >> 5, lane = t & 31;
    if (lane == 0) { rs[wid] = s; rq[wid] = sq; }
    __syncthreads();
    if (t == 0) {
        float S = 0.f, Q = 0.f;
        #pragma unroll
        for (int i = 0; i < 8; i++) { S += rs[i]; Q += rq[i]; }
        float mean = S * (1.0f / Dn);
        float var  = Q * (1.0f / Dn) - mean * mean;
        rs[0] = mean;
        rq[0] = rsqrtf(var + 1e-5f);
    }
    __syncthreads();
    const float mean = rs[0], rstd = rq[0];

    float4 gv = *(const float4*)(G + t * 4);
    float4 bv = *(const float4*)(Bt + t * 4);
    float4 y;
    y.x = (v.x - mean) * rstd * gv.x + bv.x;
    y.y = (v.y - mean) * rstd * gv.y + bv.y;
    y.z = (v.z - mean) * rstd * gv.z + bv.z;
    y.w = (v.w - mean) * rstd * gv.w + bv.w;
    *(float4*)(Y + (size_t)row * Dn + t * 4) = y;
    if (Yh) {
        __half2 h0 = __floats2half2_rn(y.x, y.y);
        __half2 h1 = __floats2half2_rn(y.z, y.w);
        *(uint2*)(Yh + (size_t)row * Dn + t * 4) =
            make_uint2(*(uint32_t*)&h0, *(uint32_t*)&h1);
    }
}

// ---------------- launch ----------------
extern "C" void kernel_launch(void* const* d_in, const int* in_sizes, int n_in,
                              void* d_out, int out_size) {
    const float* x   = (const float*)d_in[0];
    const float* wq  = (const float*)d_in[1];
    const float* bq  = (const float*)d_in[2];
    const float* wk  = (const float*)d_in[3];
    const float* bk  = (const float*)d_in[4];
    const float* wv  = (const float*)d_in[5];
    const float* bv  = (const float*)d_in[6];
    const float* wo  = (const float*)d_in[7];
    const float* bo  = (const float*)d_in[8];
    const float* w1  = (const float*)d_in[9];
    const float* b1  = (const float*)d_in[10];
    const float* w2  = (const float*)d_in[11];
    const float* b2  = (const float*)d_in[12];
    const float* g1  = (const float*)d_in[13];
    const float* be1 = (const float*)d_in[14];
    const float* g2  = (const float*)d_in[15];
    const float* be2 = (const float*)d_in[16];

    __half *WqkvT, *WoT, *W1T, *W2T, *xh, *QKVh, *Vth, *Oh, *Hhh, *FFh;
    float *Bqkv, *T, *Hh;
    cudaGetSymbolAddress((void**)&WqkvT, g_WqkvT);
    cudaGetSymbolAddress((void**)&Bqkv,  g_Bqkv);
    cudaGetSymbolAddress((void**)&WoT,   g_WoT);
    cudaGetSymbolAddress((void**)&W1T,   g_W1T);
    cudaGetSymbolAddress((void**)&W2T,   g_W2T);
    cudaGetSymbolAddress((void**)&xh,    g_xh);
    cudaGetSymbolAddress((void**)&QKVh,  g_QKVh);
    cudaGetSymbolAddress((void**)&Vth,   g_Vth);
    cudaGetSymbolAddress((void**)&Oh,    g_Oh);
    cudaGetSymbolAddress((void**)&T,     g_T);
    cudaGetSymbolAddress((void**)&Hh,    g_Hh);
    cudaGetSymbolAddress((void**)&Hhh,   g_Hhh);
    cudaGetSymbolAddress((void**)&FFh,   g_FFh);

    // 0) weight repacks + x -> fp16
    repack_qkvT<<<(3 * Dn * Dn + 255) / 256, 256>>>(wq, wk, wv, bq, bk, bv);
    transpose_kh<<<dim3(Dn / 32, Dn / 32),  dim3(32, 8)>>>(WoT, wo, Dn, Dn);
    transpose_kh<<<dim3(FFn / 32, Dn / 32), dim3(32, 8)>>>(W1T, w1, Dn, FFn);
    transpose_kh<<<dim3(Dn / 32, FFn / 32), dim3(32, 8)>>>(W2T, w2, FFn, Dn);
    f2h<<<(Mn * Dn / 4 + 255) / 256, 256>>>(x, xh, Mn * Dn / 4);

    // 1) QKV projection -> fp16
    hgemm<EPI_BIASH><<<dim3(3 * Dn / 128, Mn / 128), 128>>>(
        xh, WqkvT, Bqkv, nullptr, nullptr, QKVh, Mn, 3 * Dn, Dn);
    // 1b) V transpose per head
    vtrans<<<dim3(Sn / 32, HDn / 32, 64), dim3(32, 8)>>>(QKVh, Vth);
    // 2) tensor-core causal flash attention -> Oh (fp16)
    fattn<<<dim3(Sn / 64, 64), 128>>>(QKVh, Vth, Oh);
    // 3) O projection + residual x
    hgemm<EPI_RES><<<dim3(Dn / 128, Mn / 128), 128>>>(
        Oh, WoT, bo, x, T, nullptr, Mn, Dn, Dn);
    // 4) LayerNorm 1 (fp32 + fp16 twin)
    ln_kernel<<<Mn, 256>>>(T, g1, be1, Hh, Hhh);
    // 5) FFN up + exact GELU -> fp16
    hgemm<EPI_GELUH><<<dim3(FFn / 128, Mn / 128), 128>>>(
        Hhh, W1T, b1, nullptr, nullptr, FFh, Mn, FFn, Dn);
    // 6) FFN down + residual Hh
    hgemm<EPI_RES><<<dim3(Dn / 128, Mn / 128), 128>>>(
        FFh, W2T, b2, Hh, T, nullptr, Mn, Dn, FFn);
    // 7) LayerNorm 2 -> output
    ln_kernel<<<Mn, 256>>>(T, g2, be2, (float*)d_out, nullptr);
}